// round 2
// baseline (speedup 1.0000x reference)
#include <cuda_runtime.h>
#include <cstdint>
#include <cstddef>

#define B_    32768
#define T_    3
#define D_    64
#define H_    32
#define LH_   64
#define NBLK  128   // B_/256

// ---------------- scratch (device globals: allocation-free) ----------------
__device__ float g_h1[(size_t)T_ * B_ * H_];
__device__ float g_h2[(size_t)T_ * B_ * H_];
__device__ unsigned long long g_xg[(size_t)T_ * 128 * B_]; // xg pairs [t][j/2][r]
__device__ float g_ps1[T_ * NBLK * H_];
__device__ float g_pq1[T_ * NBLK * H_];
__device__ float g_ps2[T_ * NBLK * H_];
__device__ float g_pq2[T_ * NBLK * H_];
__device__ float2 g_bn1[T_ * H_];   // (scale, shift)
__device__ float2 g_bn2[T_ * H_];

// packed fp32x2 FMA: acc = w * h + acc
#define FMA2(a, b, c) asm("fma.rn.f32x2 %0, %1, %2, %0;" : "+l"(a) : "l"(b), "l"(c))
#define UNPK(v, lo, hi) do { unsigned _l, _h; \
    asm("mov.b64 {%0,%1}, %2;" : "=r"(_l), "=r"(_h) : "l"(v)); \
    lo = __uint_as_float(_l); hi = __uint_as_float(_h); } while (0)

__device__ __forceinline__ float sigf(float x) {
    float e = __expf(-x);
    float r;
    asm("rcp.approx.f32 %0, %1;" : "=f"(r) : "f"(1.f + e));
    return r;
}
__device__ __forceinline__ float tanhx(float x) {
    return __fmaf_rn(2.f, sigf(2.f * x), -1.f);
}

// ---------------- stage 1: h1 = x @ W1^T + b1, + batch partials ----------------
__global__ void __launch_bounds__(256) k_mlp1(const float* __restrict__ x,
                                              const float* __restrict__ W1,
                                              const float* __restrict__ b1) {
    __shared__ float sW[D_ * H_];
    __shared__ float sr0[8 * 32], sr1[8 * 32];
    int tid = threadIdx.x;
    int t = blockIdx.y;
    int r = blockIdx.x * 256 + tid;
    for (int i = tid; i < D_ * H_; i += 256) { int j = i >> 6, k = i & 63; sW[k * H_ + j] = W1[i]; }
    __syncthreads();

    float xr[64];
    const float4* xp = (const float4*)(x + ((size_t)t * B_ + r) * D_);
#pragma unroll
    for (int i = 0; i < 16; i++) {
        float4 v = xp[i];
        xr[4*i] = v.x; xr[4*i+1] = v.y; xr[4*i+2] = v.z; xr[4*i+3] = v.w;
    }
    float acc[32];
#pragma unroll
    for (int j = 0; j < 32; j++) acc[j] = __ldg(&b1[j]);
#pragma unroll
    for (int k = 0; k < 64; k++) {
        float xk = xr[k];
#pragma unroll
        for (int q = 0; q < 8; q++) {
            float4 w = *(const float4*)&sW[k * H_ + q * 4];
            acc[q*4+0] = fmaf(w.x, xk, acc[q*4+0]);
            acc[q*4+1] = fmaf(w.y, xk, acc[q*4+1]);
            acc[q*4+2] = fmaf(w.z, xk, acc[q*4+2]);
            acc[q*4+3] = fmaf(w.w, xk, acc[q*4+3]);
        }
    }
    float4* op = (float4*)(g_h1 + ((size_t)t * B_ + r) * H_);
#pragma unroll
    for (int q = 0; q < 8; q++) op[q] = make_float4(acc[q*4], acc[q*4+1], acc[q*4+2], acc[q*4+3]);

    int lane = tid & 31, wp = tid >> 5;
#pragma unroll
    for (int j = 0; j < 32; j++) {
        float s = acc[j], q = acc[j] * acc[j];
#pragma unroll
        for (int o = 16; o; o >>= 1) {
            s += __shfl_xor_sync(0xffffffffu, s, o);
            q += __shfl_xor_sync(0xffffffffu, q, o);
        }
        if (lane == 0) { sr0[wp * 32 + j] = s; sr1[wp * 32 + j] = q; }
    }
    __syncthreads();
    if (tid < 32) {
        float s = 0.f, q = 0.f;
#pragma unroll
        for (int w2 = 0; w2 < 8; w2++) { s += sr0[w2 * 32 + tid]; q += sr1[w2 * 32 + tid]; }
        g_ps1[(t * NBLK + blockIdx.x) * 32 + tid] = s;
        g_pq1[(t * NBLK + blockIdx.x) * 32 + tid] = q;
    }
}

// ---------------- BN stats reduce: (mean,var) -> (scale,shift) ----------------
__global__ void k_stats(int which, const float* __restrict__ gam, const float* __restrict__ bet) {
    int i = threadIdx.x;
    if (i >= 96) return;
    int t = i >> 5, ch = i & 31;
    const float* ps = which ? g_ps2 : g_ps1;
    const float* pq = which ? g_pq2 : g_pq1;
    float s = 0.f, q = 0.f;
    for (int b = 0; b < NBLK; b++) {
        s += ps[(t * NBLK + b) * 32 + ch];
        q += pq[(t * NBLK + b) * 32 + ch];
    }
    float m = s * (1.f / B_);
    float v = q * (1.f / B_) - m * m;
    float sc = gam[ch] * rsqrtf(v + 1e-5f);
    float2 o = make_float2(sc, bet[ch] - m * sc);
    if (which) g_bn2[i] = o; else g_bn1[i] = o;
}

// ---------------- stage 2: h2 = relu(BN1(h1)) @ W2^T + b2, + partials ----------------
__global__ void __launch_bounds__(256) k_mlp2(const float* __restrict__ W2,
                                              const float* __restrict__ b2) {
    __shared__ float sW[H_ * H_];
    __shared__ float sr0[8 * 32], sr1[8 * 32];
    int tid = threadIdx.x;
    int t = blockIdx.y;
    int r = blockIdx.x * 256 + tid;
    for (int i = tid; i < H_ * H_; i += 256) { int j = i >> 5, k = i & 31; sW[k * H_ + j] = W2[i]; }
    __syncthreads();

    float a[32];
    const float4* hp = (const float4*)(g_h1 + ((size_t)t * B_ + r) * H_);
#pragma unroll
    for (int i = 0; i < 8; i++) {
        float4 v = hp[i];
        float2 s0 = g_bn1[t * 32 + i * 4 + 0]; a[i*4+0] = fmaxf(0.f, fmaf(v.x, s0.x, s0.y));
        float2 s1 = g_bn1[t * 32 + i * 4 + 1]; a[i*4+1] = fmaxf(0.f, fmaf(v.y, s1.x, s1.y));
        float2 s2 = g_bn1[t * 32 + i * 4 + 2]; a[i*4+2] = fmaxf(0.f, fmaf(v.z, s2.x, s2.y));
        float2 s3 = g_bn1[t * 32 + i * 4 + 3]; a[i*4+3] = fmaxf(0.f, fmaf(v.w, s3.x, s3.y));
    }
    float acc[32];
#pragma unroll
    for (int j = 0; j < 32; j++) acc[j] = __ldg(&b2[j]);
#pragma unroll
    for (int k = 0; k < 32; k++) {
        float ak = a[k];
#pragma unroll
        for (int q = 0; q < 8; q++) {
            float4 w = *(const float4*)&sW[k * H_ + q * 4];
            acc[q*4+0] = fmaf(w.x, ak, acc[q*4+0]);
            acc[q*4+1] = fmaf(w.y, ak, acc[q*4+1]);
            acc[q*4+2] = fmaf(w.z, ak, acc[q*4+2]);
            acc[q*4+3] = fmaf(w.w, ak, acc[q*4+3]);
        }
    }
    float4* op = (float4*)(g_h2 + ((size_t)t * B_ + r) * H_);
#pragma unroll
    for (int q = 0; q < 8; q++) op[q] = make_float4(acc[q*4], acc[q*4+1], acc[q*4+2], acc[q*4+3]);

    int lane = tid & 31, wp = tid >> 5;
#pragma unroll
    for (int j = 0; j < 32; j++) {
        float s = acc[j], q = acc[j] * acc[j];
#pragma unroll
        for (int o = 16; o; o >>= 1) {
            s += __shfl_xor_sync(0xffffffffu, s, o);
            q += __shfl_xor_sync(0xffffffffu, q, o);
        }
        if (lane == 0) { sr0[wp * 32 + j] = s; sr1[wp * 32 + j] = q; }
    }
    __syncthreads();
    if (tid < 32) {
        float s = 0.f, q = 0.f;
#pragma unroll
        for (int w2 = 0; w2 < 8; w2++) { s += sr0[w2 * 32 + tid]; q += sr1[w2 * 32 + tid]; }
        g_ps2[(t * NBLK + blockIdx.x) * 32 + tid] = s;
        g_pq2[(t * NBLK + blockIdx.x) * 32 + tid] = q;
    }
}

// ---- stage 3: enc = relu(BN2(h2)) @ W3^T + b3; xg = enc @ Wih^T + (bih+bhh) ----
__global__ void __launch_bounds__(256) k_mlp3(const float* __restrict__ W3,
                                              const float* __restrict__ b3,
                                              const float* __restrict__ Wih,
                                              const float* __restrict__ bih,
                                              const float* __restrict__ bhh) {
    extern __shared__ __align__(16) float sm5[];
    float* sW3 = sm5;                    // [k<32][j<64]   2048 f
    float* sWi = sm5 + 2048;             // [k<64][j<256] 16384 f
    float* sb  = sm5 + 2048 + 16384;     // 256 f (8B-aligned: offset even)
    int tid = threadIdx.x;
    int t = blockIdx.y;
    int r = blockIdx.x * 256 + tid;
    for (int i = tid; i < 2048; i += 256)  { int j = i >> 5, k = i & 31; sW3[k * 64 + j] = W3[i]; }
    for (int i = tid; i < 16384; i += 256) { int j = i >> 6, k = i & 63; sWi[k * 256 + j] = Wih[i]; }
    sb[tid] = bih[tid] + bhh[tid];
    __syncthreads();

    float a[32];
    const float4* hp = (const float4*)(g_h2 + ((size_t)t * B_ + r) * H_);
#pragma unroll
    for (int i = 0; i < 8; i++) {
        float4 v = hp[i];
        float2 s0 = g_bn2[t * 32 + i * 4 + 0]; a[i*4+0] = fmaxf(0.f, fmaf(v.x, s0.x, s0.y));
        float2 s1 = g_bn2[t * 32 + i * 4 + 1]; a[i*4+1] = fmaxf(0.f, fmaf(v.y, s1.x, s1.y));
        float2 s2 = g_bn2[t * 32 + i * 4 + 2]; a[i*4+2] = fmaxf(0.f, fmaf(v.z, s2.x, s2.y));
        float2 s3 = g_bn2[t * 32 + i * 4 + 3]; a[i*4+3] = fmaxf(0.f, fmaf(v.w, s3.x, s3.y));
    }
    float e[64];
#pragma unroll
    for (int j = 0; j < 64; j++) e[j] = __ldg(&b3[j]);
#pragma unroll
    for (int k = 0; k < 32; k++) {
        float ak = a[k];
#pragma unroll
        for (int q = 0; q < 16; q++) {
            float4 w = *(const float4*)&sW3[k * 64 + q * 4];
            e[q*4+0] = fmaf(w.x, ak, e[q*4+0]);
            e[q*4+1] = fmaf(w.y, ak, e[q*4+1]);
            e[q*4+2] = fmaf(w.z, ak, e[q*4+2]);
            e[q*4+3] = fmaf(w.w, ak, e[q*4+3]);
        }
    }
    // xg = e @ Wih^T + bsum, packed pairs, layout [t][pair j/2][r]
    unsigned long long* xgw = g_xg + (size_t)t * 128 * B_ + r;
#pragma unroll 1
    for (int c = 0; c < 16; c++) {
        int j0 = c * 16;
        unsigned long long acc[8];
#pragma unroll
        for (int p = 0; p < 8; p++) acc[p] = *(const unsigned long long*)&sb[j0 + 2 * p];
#pragma unroll
        for (int k = 0; k < 64; k++) {
            unsigned long long hk;
            asm("mov.b64 %0, {%1,%1};" : "=l"(hk) : "r"(__float_as_uint(e[k])));
            const ulonglong2* wv = (const ulonglong2*)&sWi[k * 256 + j0];
            ulonglong2 w0 = wv[0], w1 = wv[1], w2 = wv[2], w3 = wv[3];
            FMA2(acc[0], w0.x, hk); FMA2(acc[1], w0.y, hk);
            FMA2(acc[2], w1.x, hk); FMA2(acc[3], w1.y, hk);
            FMA2(acc[4], w2.x, hk); FMA2(acc[5], w2.y, hk);
            FMA2(acc[6], w3.x, hk); FMA2(acc[7], w3.y, hk);
        }
#pragma unroll
        for (int p = 0; p < 8; p++) xgw[(size_t)(c * 8 + p) * B_] = acc[p];
    }
}

// ---------------- stage 4: fused 28-step LSTM, one thread per batch row ----------------
// smem: sW [64][256] (Whh for steps 0..3, then += Wih), sH double-buffer [128][256], sb [256]
__global__ void __launch_bounds__(256, 1) k_lstm(const float* __restrict__ Wih,
                                                 const float* __restrict__ Whh,
                                                 const float* __restrict__ bih,
                                                 const float* __restrict__ bhh,
                                                 float* __restrict__ out) {
    extern __shared__ __align__(16) float sm6[];
    float* sW = sm6;                 // 16384 f
    float* sH = sm6 + 16384;         // 32768 f (2 banks of [64][256])
    float* sb = sm6 + 16384 + 32768; // 256 f
    int tid = threadIdx.x;
    int r = blockIdx.x * 256 + tid;

    for (int i = tid; i < 16384; i += 256) { int j = i >> 6, k = i & 63; sW[k * 256 + j] = Whh[i]; }
    sb[tid] = bih[tid] + bhh[tid];
#pragma unroll
    for (int k = 0; k < 64; k++) sH[k * 256 + tid] = 0.f;
    __syncthreads();

    float c[64];
#pragma unroll
    for (int d = 0; d < 64; d++) c[d] = 0.f;

#pragma unroll 1
    for (int step = 0; step < 28; step++) {
        if (step == 4) {
            __syncthreads();
            for (int i = tid; i < 16384; i += 256) { int j = i >> 6, k = i & 63; sW[k * 256 + j] += Wih[i]; }
            __syncthreads();
        }
        bool useX = step < 4;
        int t = (step < 3) ? step : 2;
        const unsigned long long* xrow = g_xg + (size_t)t * 128 * B_ + r;
        const float* sHr = sH + (step & 1) * 16384;
        float* sHw = sH + ((step & 1) ^ 1) * 16384;

#pragma unroll
        for (int cd = 0; cd < 8; cd++) {
            const int d0 = cd * 8;
            unsigned long long acc[16];
            if (useX) {
#pragma unroll
                for (int g = 0; g < 4; g++)
#pragma unroll
                    for (int p = 0; p < 4; p++)
                        acc[g*4+p] = xrow[(size_t)(g * 32 + (d0 >> 1) + p) * B_];
            } else {
#pragma unroll
                for (int g = 0; g < 4; g++)
#pragma unroll
                    for (int p = 0; p < 4; p++)
                        acc[g*4+p] = *(const unsigned long long*)&sb[g * 64 + d0 + 2 * p];
            }
#pragma unroll 2
            for (int k = 0; k < 64; k++) {
                float hk = sHr[k * 256 + tid];
                unsigned long long hd;
                asm("mov.b64 %0, {%1,%1};" : "=l"(hd) : "r"(__float_as_uint(hk)));
#pragma unroll
                for (int g = 0; g < 4; g++) {
                    ulonglong2 w0 = *(const ulonglong2*)&sW[k * 256 + g * 64 + d0];
                    ulonglong2 w1 = *(const ulonglong2*)&sW[k * 256 + g * 64 + d0 + 4];
                    FMA2(acc[g*4+0], w0.x, hd);
                    FMA2(acc[g*4+1], w0.y, hd);
                    FMA2(acc[g*4+2], w1.x, hd);
                    FMA2(acc[g*4+3], w1.y, hd);
                }
            }
            float hv[8];
#pragma unroll
            for (int p = 0; p < 4; p++) {
                float i0, i1, f0, f1, g0, g1, o0, o1;
                UNPK(acc[0*4+p], i0, i1);
                UNPK(acc[1*4+p], f0, f1);
                UNPK(acc[2*4+p], g0, g1);
                UNPK(acc[3*4+p], o0, o1);
                int d = d0 + 2 * p;
                float cn0 = sigf(f0) * c[d]     + sigf(i0) * tanhx(g0);
                float cn1 = sigf(f1) * c[d + 1] + sigf(i1) * tanhx(g1);
                c[d] = cn0; c[d + 1] = cn1;
                hv[2*p]   = sigf(o0) * tanhx(cn0);
                hv[2*p+1] = sigf(o1) * tanhx(cn1);
            }
#pragma unroll
            for (int d = 0; d < 8; d++) sHw[(d0 + d) * 256 + tid] = hv[d];
            if (step >= 3) {
                float4* op = (float4*)(out + ((size_t)r * 25 + (step - 3)) * 64 + d0);
                op[0] = make_float4(hv[0], hv[1], hv[2], hv[3]);
                op[1] = make_float4(hv[4], hv[5], hv[6], hv[7]);
            }
        }
    }
}

// ---------------- host ----------------
extern "C" void kernel_launch(void* const* d_in, const int* in_sizes, int n_in,
                              void* d_out, int out_size) {
    const float* x   = (const float*)d_in[0];
    const float* W1  = (const float*)d_in[1];
    const float* b1  = (const float*)d_in[2];
    const float* g1  = (const float*)d_in[3];
    const float* be1 = (const float*)d_in[4];
    const float* W2  = (const float*)d_in[5];
    const float* b2  = (const float*)d_in[6];
    const float* g2  = (const float*)d_in[7];
    const float* be2 = (const float*)d_in[8];
    const float* W3  = (const float*)d_in[9];
    const float* b3  = (const float*)d_in[10];
    const float* Wih = (const float*)d_in[11];
    const float* Whh = (const float*)d_in[12];
    const float* bih = (const float*)d_in[13];
    const float* bhh = (const float*)d_in[14];
    float* out = (float*)d_out;

    static bool attr_done = false;
    if (!attr_done) {
        cudaFuncSetAttribute(k_mlp3, cudaFuncAttributeMaxDynamicSharedMemorySize, 18688 * 4);
        cudaFuncSetAttribute(k_lstm, cudaFuncAttributeMaxDynamicSharedMemorySize, 49408 * 4);
        attr_done = true;
    }

    dim3 gmlp(NBLK, T_);
    k_mlp1<<<gmlp, 256>>>(x, W1, b1);
    k_stats<<<1, 128>>>(0, g1, be1);
    k_mlp2<<<gmlp, 256>>>(W2, b2);
    k_stats<<<1, 128>>>(1, g2, be2);
    k_mlp3<<<gmlp, 256, 18688 * 4>>>(W3, b3, Wih, bih, bhh);
    k_lstm<<<NBLK, 256, 49408 * 4>>>(Wih, Whh, bih, bhh, out);
}

// round 4
// speedup vs baseline: 1.9512x; 1.9512x over previous
#include <cuda_runtime.h>
#include <cuda_bf16.h>
#include <cstdint>
#include <cstddef>

#define B_    32768
#define T_    3
#define D_    64
#define H_    32
#define NBLK  128   // B_/256

// ---------------- scratch (device globals: allocation-free) ----------------
__device__ float g_h1[(size_t)T_ * B_ * H_];
__device__ float g_h2[(size_t)T_ * B_ * H_];
__device__ unsigned long long g_xg[(size_t)T_ * 128 * B_]; // xg pairs [t][j/2][r]
__device__ float g_ps1[T_ * NBLK * H_];
__device__ float g_pq1[T_ * NBLK * H_];
__device__ float g_ps2[T_ * NBLK * H_];
__device__ float g_pq2[T_ * NBLK * H_];
__device__ float2 g_bn1[T_ * H_];   // (scale, shift)
__device__ float2 g_bn2[T_ * H_];
// weight tiles: 4 x [256 n][64 k] bf16, 128B rows, SW128-swizzled
// tile 0 = Whh_hi, 1 = Whh_lo, 2 = (Wih+Whh)_hi, 3 = (Wih+Whh)_lo
__device__ __align__(16) uint8_t g_wt[4 * 32768];

// packed fp32x2 FMA: acc = w * h + acc
#define FMA2(a, b, c) asm("fma.rn.f32x2 %0, %1, %2, %0;" : "+l"(a) : "l"(b), "l"(c))
#define UNPK(v, lo, hi) do { unsigned _l, _h; \
    asm("mov.b64 {%0,%1}, %2;" : "=r"(_l), "=r"(_h) : "l"(v)); \
    lo = __uint_as_float(_l); hi = __uint_as_float(_h); } while (0)

__device__ __forceinline__ float sigf(float x) {
    float e = __expf(-x);
    float r;
    asm("rcp.approx.f32 %0, %1;" : "=f"(r) : "f"(1.f + e));
    return r;
}
__device__ __forceinline__ float tanhx(float x) {
    return __fmaf_rn(2.f, sigf(2.f * x), -1.f);
}
__host__ __device__ __forceinline__ uint32_t swz128(uint32_t o) {
    return o ^ ((o >> 3) & 0x70);
}

// ---------------- stage 1: h1 = x @ W1^T + b1, + batch partials ----------------
__global__ void __launch_bounds__(256) k_mlp1(const float* __restrict__ x,
                                              const float* __restrict__ W1,
                                              const float* __restrict__ b1) {
    __shared__ float sW[D_ * H_];
    __shared__ float sr0[8 * 32], sr1[8 * 32];
    int tid = threadIdx.x;
    int t = blockIdx.y;
    int r = blockIdx.x * 256 + tid;
    for (int i = tid; i < D_ * H_; i += 256) { int j = i >> 6, k = i & 63; sW[k * H_ + j] = W1[i]; }
    __syncthreads();

    float xr[64];
    const float4* xp = (const float4*)(x + ((size_t)t * B_ + r) * D_);
#pragma unroll
    for (int i = 0; i < 16; i++) {
        float4 v = xp[i];
        xr[4*i] = v.x; xr[4*i+1] = v.y; xr[4*i+2] = v.z; xr[4*i+3] = v.w;
    }
    float acc[32];
#pragma unroll
    for (int j = 0; j < 32; j++) acc[j] = __ldg(&b1[j]);
#pragma unroll
    for (int k = 0; k < 64; k++) {
        float xk = xr[k];
#pragma unroll
        for (int q = 0; q < 8; q++) {
            float4 w = *(const float4*)&sW[k * H_ + q * 4];
            acc[q*4+0] = fmaf(w.x, xk, acc[q*4+0]);
            acc[q*4+1] = fmaf(w.y, xk, acc[q*4+1]);
            acc[q*4+2] = fmaf(w.z, xk, acc[q*4+2]);
            acc[q*4+3] = fmaf(w.w, xk, acc[q*4+3]);
        }
    }
    float4* op = (float4*)(g_h1 + ((size_t)t * B_ + r) * H_);
#pragma unroll
    for (int q = 0; q < 8; q++) op[q] = make_float4(acc[q*4], acc[q*4+1], acc[q*4+2], acc[q*4+3]);

    int lane = tid & 31, wp = tid >> 5;
#pragma unroll
    for (int j = 0; j < 32; j++) {
        float s = acc[j], q = acc[j] * acc[j];
#pragma unroll
        for (int o = 16; o; o >>= 1) {
            s += __shfl_xor_sync(0xffffffffu, s, o);
            q += __shfl_xor_sync(0xffffffffu, q, o);
        }
        if (lane == 0) { sr0[wp * 32 + j] = s; sr1[wp * 32 + j] = q; }
    }
    __syncthreads();
    if (tid < 32) {
        float s = 0.f, q = 0.f;
#pragma unroll
        for (int w2 = 0; w2 < 8; w2++) { s += sr0[w2 * 32 + tid]; q += sr1[w2 * 32 + tid]; }
        g_ps1[(t * NBLK + blockIdx.x) * 32 + tid] = s;
        g_pq1[(t * NBLK + blockIdx.x) * 32 + tid] = q;
    }
}

// ---------------- BN stats reduce (parallel: 3 blocks x 256 thr) ----------------
__global__ void k_stats(int which, const float* __restrict__ gam, const float* __restrict__ bet) {
    __shared__ float ss[256], sq[256];
    int t = blockIdx.x;
    int tid = threadIdx.x;
    int ch = tid & 31, part = tid >> 5;   // 8 parts x 16 blocks
    const float* ps = which ? g_ps2 : g_ps1;
    const float* pq = which ? g_pq2 : g_pq1;
    float s = 0.f, q = 0.f;
#pragma unroll
    for (int b = 0; b < 16; b++) {
        int blk = part * 16 + b;
        s += ps[(t * NBLK + blk) * 32 + ch];
        q += pq[(t * NBLK + blk) * 32 + ch];
    }
    ss[tid] = s; sq[tid] = q;
    __syncthreads();
    if (tid < 32) {
#pragma unroll
        for (int p = 1; p < 8; p++) { s += ss[p * 32 + tid]; q += sq[p * 32 + tid]; }
        float m = s * (1.f / B_);
        float v = q * (1.f / B_) - m * m;
        float sc = gam[tid] * rsqrtf(v + 1e-5f);
        float2 o = make_float2(sc, bet[tid] - m * sc);
        if (which) g_bn2[t * 32 + tid] = o; else g_bn1[t * 32 + tid] = o;
    }
}

// ---------------- stage 2: h2 = relu(BN1(h1)) @ W2^T + b2, + partials ----------------
__global__ void __launch_bounds__(256) k_mlp2(const float* __restrict__ W2,
                                              const float* __restrict__ b2) {
    __shared__ float sW[H_ * H_];
    __shared__ float sr0[8 * 32], sr1[8 * 32];
    int tid = threadIdx.x;
    int t = blockIdx.y;
    int r = blockIdx.x * 256 + tid;
    for (int i = tid; i < H_ * H_; i += 256) { int j = i >> 5, k = i & 31; sW[k * H_ + j] = W2[i]; }
    __syncthreads();

    float a[32];
    const float4* hp = (const float4*)(g_h1 + ((size_t)t * B_ + r) * H_);
#pragma unroll
    for (int i = 0; i < 8; i++) {
        float4 v = hp[i];
        float2 s0 = g_bn1[t * 32 + i * 4 + 0]; a[i*4+0] = fmaxf(0.f, fmaf(v.x, s0.x, s0.y));
        float2 s1 = g_bn1[t * 32 + i * 4 + 1]; a[i*4+1] = fmaxf(0.f, fmaf(v.y, s1.x, s1.y));
        float2 s2 = g_bn1[t * 32 + i * 4 + 2]; a[i*4+2] = fmaxf(0.f, fmaf(v.z, s2.x, s2.y));
        float2 s3 = g_bn1[t * 32 + i * 4 + 3]; a[i*4+3] = fmaxf(0.f, fmaf(v.w, s3.x, s3.y));
    }
    float acc[32];
#pragma unroll
    for (int j = 0; j < 32; j++) acc[j] = __ldg(&b2[j]);
#pragma unroll
    for (int k = 0; k < 32; k++) {
        float ak = a[k];
#pragma unroll
        for (int q = 0; q < 8; q++) {
            float4 w = *(const float4*)&sW[k * H_ + q * 4];
            acc[q*4+0] = fmaf(w.x, ak, acc[q*4+0]);
            acc[q*4+1] = fmaf(w.y, ak, acc[q*4+1]);
            acc[q*4+2] = fmaf(w.z, ak, acc[q*4+2]);
            acc[q*4+3] = fmaf(w.w, ak, acc[q*4+3]);
        }
    }
    float4* op = (float4*)(g_h2 + ((size_t)t * B_ + r) * H_);
#pragma unroll
    for (int q = 0; q < 8; q++) op[q] = make_float4(acc[q*4], acc[q*4+1], acc[q*4+2], acc[q*4+3]);

    int lane = tid & 31, wp = tid >> 5;
#pragma unroll
    for (int j = 0; j < 32; j++) {
        float s = acc[j], q = acc[j] * acc[j];
#pragma unroll
        for (int o = 16; o; o >>= 1) {
            s += __shfl_xor_sync(0xffffffffu, s, o);
            q += __shfl_xor_sync(0xffffffffu, q, o);
        }
        if (lane == 0) { sr0[wp * 32 + j] = s; sr1[wp * 32 + j] = q; }
    }
    __syncthreads();
    if (tid < 32) {
        float s = 0.f, q = 0.f;
#pragma unroll
        for (int w2 = 0; w2 < 8; w2++) { s += sr0[w2 * 32 + tid]; q += sr1[w2 * 32 + tid]; }
        g_ps2[(t * NBLK + blockIdx.x) * 32 + tid] = s;
        g_pq2[(t * NBLK + blockIdx.x) * 32 + tid] = q;
    }
}

// ---- stage 3: enc = relu(BN2(h2)) @ W3^T + b3; xg = enc @ Wih^T + (bih+bhh) ----
__global__ void __launch_bounds__(256) k_mlp3(const float* __restrict__ W3,
                                              const float* __restrict__ b3,
                                              const float* __restrict__ Wih,
                                              const float* __restrict__ bih,
                                              const float* __restrict__ bhh) {
    extern __shared__ __align__(16) float sm5[];
    float* sW3 = sm5;                    // [k<32][j<64]   2048 f
    float* sWi = sm5 + 2048;             // [k<64][j<256] 16384 f
    float* sb  = sm5 + 2048 + 16384;     // 256 f
    int tid = threadIdx.x;
    int t = blockIdx.y;
    int r = blockIdx.x * 256 + tid;
    for (int i = tid; i < 2048; i += 256)  { int j = i >> 5, k = i & 31; sW3[k * 64 + j] = W3[i]; }
    for (int i = tid; i < 16384; i += 256) { int j = i >> 6, k = i & 63; sWi[k * 256 + j] = Wih[i]; }
    sb[tid] = bih[tid] + bhh[tid];
    __syncthreads();

    float a[32];
    const float4* hp = (const float4*)(g_h2 + ((size_t)t * B_ + r) * H_);
#pragma unroll
    for (int i = 0; i < 8; i++) {
        float4 v = hp[i];
        float2 s0 = g_bn2[t * 32 + i * 4 + 0]; a[i*4+0] = fmaxf(0.f, fmaf(v.x, s0.x, s0.y));
        float2 s1 = g_bn2[t * 32 + i * 4 + 1]; a[i*4+1] = fmaxf(0.f, fmaf(v.y, s1.x, s1.y));
        float2 s2 = g_bn2[t * 32 + i * 4 + 2]; a[i*4+2] = fmaxf(0.f, fmaf(v.z, s2.x, s2.y));
        float2 s3 = g_bn2[t * 32 + i * 4 + 3]; a[i*4+3] = fmaxf(0.f, fmaf(v.w, s3.x, s3.y));
    }
    float e[64];
#pragma unroll
    for (int j = 0; j < 64; j++) e[j] = __ldg(&b3[j]);
#pragma unroll
    for (int k = 0; k < 32; k++) {
        float ak = a[k];
#pragma unroll
        for (int q = 0; q < 16; q++) {
            float4 w = *(const float4*)&sW3[k * 64 + q * 4];
            e[q*4+0] = fmaf(w.x, ak, e[q*4+0]);
            e[q*4+1] = fmaf(w.y, ak, e[q*4+1]);
            e[q*4+2] = fmaf(w.z, ak, e[q*4+2]);
            e[q*4+3] = fmaf(w.w, ak, e[q*4+3]);
        }
    }
    // xg = e @ Wih^T + bsum, packed pairs, layout [t][pair j/2][r]
    unsigned long long* xgw = g_xg + (size_t)t * 128 * B_ + r;
#pragma unroll 1
    for (int c = 0; c < 16; c++) {
        int j0 = c * 16;
        unsigned long long acc[8];
#pragma unroll
        for (int p = 0; p < 8; p++) acc[p] = *(const unsigned long long*)&sb[j0 + 2 * p];
#pragma unroll
        for (int k = 0; k < 64; k++) {
            unsigned long long hk;
            asm("mov.b64 %0, {%1,%1};" : "=l"(hk) : "r"(__float_as_uint(e[k])));
            const ulonglong2* wv = (const ulonglong2*)&sWi[k * 256 + j0];
            ulonglong2 w0 = wv[0], w1 = wv[1], w2 = wv[2], w3 = wv[3];
            FMA2(acc[0], w0.x, hk); FMA2(acc[1], w0.y, hk);
            FMA2(acc[2], w1.x, hk); FMA2(acc[3], w1.y, hk);
            FMA2(acc[4], w2.x, hk); FMA2(acc[5], w2.y, hk);
            FMA2(acc[6], w3.x, hk); FMA2(acc[7], w3.y, hk);
        }
#pragma unroll
        for (int p = 0; p < 8; p++) xgw[(size_t)(c * 8 + p) * B_] = acc[p];
    }
}

// ---------------- weight split/prep for HMMA tiles ----------------
__global__ void k_prep(const float* __restrict__ Wih, const float* __restrict__ Whh) {
    int n = threadIdx.x;   // 256 rows
#pragma unroll 1
    for (int k = 0; k < 64; k++) {
        float whh = Whh[n * 64 + k];
        float wih = Wih[n * 64 + k];
        float ws = whh + wih;
        __nv_bfloat16 hh = __float2bfloat16_rn(whh);
        __nv_bfloat16 hl = __float2bfloat16_rn(whh - __bfloat162float(hh));
        __nv_bfloat16 sh = __float2bfloat16_rn(ws);
        __nv_bfloat16 sl = __float2bfloat16_rn(ws - __bfloat162float(sh));
        uint32_t off = swz128((uint32_t)(n * 128 + k * 2));
        *(__nv_bfloat16*)(g_wt + 0 * 32768 + off) = hh;
        *(__nv_bfloat16*)(g_wt + 1 * 32768 + off) = hl;
        *(__nv_bfloat16*)(g_wt + 2 * 32768 + off) = sh;
        *(__nv_bfloat16*)(g_wt + 3 * 32768 + off) = sl;
    }
}

// ---------------- HMMA helpers ----------------
__device__ __forceinline__ void mma_bf16(float d[4], const uint32_t a[4],
                                         uint32_t b0, uint32_t b1) {
    asm volatile(
        "mma.sync.aligned.m16n8k16.row.col.f32.bf16.bf16.f32 "
        "{%0,%1,%2,%3}, {%4,%5,%6,%7}, {%8,%9}, {%0,%1,%2,%3};"
        : "+f"(d[0]), "+f"(d[1]), "+f"(d[2]), "+f"(d[3])
        : "r"(a[0]), "r"(a[1]), "r"(a[2]), "r"(a[3]), "r"(b0), "r"(b1));
}
__device__ __forceinline__ void ldsm4(uint32_t r[4], uint32_t addr) {
    asm volatile("ldmatrix.sync.aligned.m8n8.x4.shared.b16 {%0,%1,%2,%3}, [%4];"
                 : "=r"(r[0]), "=r"(r[1]), "=r"(r[2]), "=r"(r[3]) : "r"(addr) : "memory");
}
__device__ __forceinline__ uint32_t pack_bf16(float lo, float hi) {
    uint32_t r;
    asm("cvt.rn.bf16x2.f32 %0, %1, %2;" : "=r"(r) : "f"(hi), "f"(lo));
    return r;
}

// smem layout (bytes): A buffers 2x(hi 32K + lo 32K) @0..131072,
// W_hi @131072, W_lo @163840, bsum @196608
#define SW_OFF   131072u
#define SBIAS    196608u
#define LSTM_SMEM 197632

// ---------------- stage 4: HMMA 28-step LSTM, 256 rows/CTA, warp-private ----------------
__global__ void __launch_bounds__(256, 1) k_lstm_mm(const float* __restrict__ bih,
                                                    const float* __restrict__ bhh,
                                                    float* __restrict__ out) {
    extern __shared__ __align__(16) uint8_t sm[];
    uint32_t smem_base;
    asm("{ .reg .u64 t; cvta.to.shared.u64 t, %1; cvt.u32.u64 %0, t; }"
        : "=r"(smem_base) : "l"(sm));
    float* sbsum = (float*)(sm + SBIAS);
    const int tid = threadIdx.x, wid = tid >> 5, lane = tid & 31;

    // load Whh hi/lo tiles + biases
    {
        const uint4* src = (const uint4*)g_wt;
        uint4* dst = (uint4*)(sm + SW_OFF);
        for (int i = tid; i < 65536 / 16; i += 256) dst[i] = src[i];
        sbsum[tid] = bih[tid] + bhh[tid];
    }
    __syncthreads();

    // per-lane address constants
    const int l7 = lane & 7;
    const uint32_t lxor = (uint32_t)l7 * 16u;
    const uint32_t aoff16 = (uint32_t)((lane >> 4) & 1) * 16u;
    const uint32_t boff16 = (uint32_t)((lane >> 3) & 1) * 16u;
    const uint32_t arow0 = (uint32_t)(wid * 32 + l7 + ((lane >> 3) & 1) * 8) * 128u;
    const uint32_t brow_l = (uint32_t)(((lane >> 4) & 1) * 8 + l7) * 128u;
    const int qr = lane >> 2, qc = lane & 3;
    const int rowL0 = wid * 32 + qr;
    const size_t rowG0 = (size_t)blockIdx.x * 256 + rowL0;

    float c[64];
#pragma unroll
    for (int i = 0; i < 64; i++) c[i] = 0.f;

#pragma unroll 1
    for (int s = 0; s < 28; s++) {
        if (s == 4) {  // swap weights: Whh -> Wih+Whh
            __syncthreads();
            const uint4* src = (const uint4*)(g_wt + 65536);
            uint4* dst = (uint4*)(sm + SW_OFF);
            for (int i = tid; i < 65536 / 16; i += 256) dst[i] = src[i];
            __syncthreads();
        }
        const uint32_t aRd = smem_base + (uint32_t)((s + 1) & 1) * 65536u;
        uint8_t* aWr = sm + (uint32_t)(s & 1) * 65536u;
        const uint32_t whi = smem_base + SW_OFF;
        const int tsel = (s < 3) ? s : 2;
        const unsigned long long* xbase = g_xg + (size_t)tsel * 128 * B_;

#pragma unroll
        for (int cd = 0; cd < 4; cd++) {
            float acc[2][4][2][4];
#pragma unroll
            for (int mt = 0; mt < 2; mt++)
#pragma unroll
                for (int g = 0; g < 4; g++)
#pragma unroll
                    for (int ds = 0; ds < 2; ds++)
#pragma unroll
                        for (int z = 0; z < 4; z++) acc[mt][g][ds][z] = 0.f;

            if (s >= 1) {
                const uint32_t brow_cd = (uint32_t)(cd * 16) * 128u + brow_l;
#pragma unroll
                for (int kt = 0; kt < 4; kt++) {
                    const uint32_t acol = ((uint32_t)(kt * 32) + aoff16) ^ lxor;
                    const uint32_t bcol = ((uint32_t)(kt * 32) + boff16) ^ lxor;
                    uint32_t ah[2][4], al[2][4];
                    ldsm4(ah[0], aRd + arow0 + acol);
                    ldsm4(ah[1], aRd + arow0 + 2048u + acol);
                    ldsm4(al[0], aRd + 32768u + arow0 + acol);
                    ldsm4(al[1], aRd + 32768u + arow0 + 2048u + acol);
                    uint32_t bh[4][4], bl[4][4];
#pragma unroll
                    for (int g = 0; g < 4; g++) {
                        ldsm4(bh[g], whi + (uint32_t)g * 8192u + brow_cd + bcol);
                        ldsm4(bl[g], whi + 32768u + (uint32_t)g * 8192u + brow_cd + bcol);
                    }
#pragma unroll
                    for (int mt = 0; mt < 2; mt++)
#pragma unroll
                        for (int g = 0; g < 4; g++)
#pragma unroll
                            for (int ds = 0; ds < 2; ds++) {
                                mma_bf16(acc[mt][g][ds], ah[mt], bh[g][ds*2], bh[g][ds*2+1]);
                                mma_bf16(acc[mt][g][ds], al[mt], bh[g][ds*2], bh[g][ds*2+1]);
                                mma_bf16(acc[mt][g][ds], ah[mt], bl[g][ds*2], bl[g][ds*2+1]);
                            }
                }
            }

            // epilogue for this 16-d chunk
            const int pbase = cd * 8 + qc;   // + ds*4 ; xg pair index base
#pragma unroll
            for (int mt = 0; mt < 2; mt++)
#pragma unroll
                for (int ds = 0; ds < 2; ds++) {
                    const int dbase = cd * 16 + ds * 8 + 2 * qc;
                    float2 bi, bf, bg, bo;
                    if (s >= 4) {
                        bi = *(const float2*)&sbsum[0 * 64 + dbase];
                        bf = *(const float2*)&sbsum[1 * 64 + dbase];
                        bg = *(const float2*)&sbsum[2 * 64 + dbase];
                        bo = *(const float2*)&sbsum[3 * 64 + dbase];
                    }
#pragma unroll
                    for (int rr = 0; rr < 2; rr++) {
                        const int rowL = rowL0 + mt * 16 + rr * 8;
                        float gi0 = acc[mt][0][ds][rr*2], gi1 = acc[mt][0][ds][rr*2+1];
                        float gf0 = acc[mt][1][ds][rr*2], gf1 = acc[mt][1][ds][rr*2+1];
                        float gg0 = acc[mt][2][ds][rr*2], gg1 = acc[mt][2][ds][rr*2+1];
                        float go0 = acc[mt][3][ds][rr*2], go1 = acc[mt][3][ds][rr*2+1];
                        if (s < 4) {
                            const unsigned long long* xp = xbase + (rowG0 + mt * 16 + rr * 8);
                            const int pi = pbase + ds * 4;
                            float lo, hi;
                            unsigned long long v;
                            v = xp[(size_t)(0 * 32 + pi) * B_]; UNPK(v, lo, hi); gi0 += lo; gi1 += hi;
                            v = xp[(size_t)(1 * 32 + pi) * B_]; UNPK(v, lo, hi); gf0 += lo; gf1 += hi;
                            v = xp[(size_t)(2 * 32 + pi) * B_]; UNPK(v, lo, hi); gg0 += lo; gg1 += hi;
                            v = xp[(size_t)(3 * 32 + pi) * B_]; UNPK(v, lo, hi); go0 += lo; go1 += hi;
                        } else {
                            gi0 += bi.x; gi1 += bi.y;
                            gf0 += bf.x; gf1 += bf.y;
                            gg0 += bg.x; gg1 += bg.y;
                            go0 += bo.x; go1 += bo.y;
                        }
                        const int ci = (((cd * 2 + ds) * 2 + mt) * 2 + rr) * 2;
                        float cn0 = sigf(gf0) * c[ci]     + sigf(gi0) * tanhx(gg0);
                        float cn1 = sigf(gf1) * c[ci + 1] + sigf(gi1) * tanhx(gg1);
                        c[ci] = cn0; c[ci + 1] = cn1;
                        float h0 = sigf(go0) * tanhx(cn0);
                        float h1 = sigf(go1) * tanhx(cn1);
                        // split h into bf16 hi/lo and store to next-step A tile
                        uint32_t ph = pack_bf16(h0, h1);
                        float e0 = h0 - __uint_as_float(ph << 16);
                        float e1 = h1 - __uint_as_float(ph & 0xffff0000u);
                        uint32_t pl = pack_bf16(e0, e1);
                        uint32_t soff = (uint32_t)rowL * 128u +
                                        (((uint32_t)(cd * 32 + ds * 16 + qc * 4)) ^ ((uint32_t)qr * 16u));
                        *(uint32_t*)(aWr + soff) = ph;
                        *(uint32_t*)(aWr + 32768u + soff) = pl;
                        if (s >= 3) {
                            float2 o2 = make_float2(h0, h1);
                            *(float2*)(out + ((rowG0 + mt * 16 + rr * 8) * 25 + (s - 3)) * 64 + dbase) = o2;
                        }
                    }
                }
        }
        __syncwarp();
    }
}

// ---------------- host ----------------
extern "C" void kernel_launch(void* const* d_in, const int* in_sizes, int n_in,
                              void* d_out, int out_size) {
    const float* x   = (const float*)d_in[0];
    const float* W1  = (const float*)d_in[1];
    const float* b1  = (const float*)d_in[2];
    const float* g1  = (const float*)d_in[3];
    const float* be1 = (const float*)d_in[4];
    const float* W2  = (const float*)d_in[5];
    const float* b2  = (const float*)d_in[6];
    const float* g2  = (const float*)d_in[7];
    const float* be2 = (const float*)d_in[8];
    const float* W3  = (const float*)d_in[9];
    const float* b3  = (const float*)d_in[10];
    const float* Wih = (const float*)d_in[11];
    const float* Whh = (const float*)d_in[12];
    const float* bih = (const float*)d_in[13];
    const float* bhh = (const float*)d_in[14];
    float* out = (float*)d_out;

    static bool attr_done = false;
    if (!attr_done) {
        cudaFuncSetAttribute(k_mlp3, cudaFuncAttributeMaxDynamicSharedMemorySize, 18688 * 4);
        cudaFuncSetAttribute(k_lstm_mm, cudaFuncAttributeMaxDynamicSharedMemorySize, LSTM_SMEM);
        attr_done = true;
    }

    dim3 gmlp(NBLK, T_);
    k_prep<<<1, 256>>>(Wih, Whh);
    k_mlp1<<<gmlp, 256>>>(x, W1, b1);
    k_stats<<<T_, 256>>>(0, g1, be1);
    k_mlp2<<<gmlp, 256>>>(W2, b2);
    k_stats<<<T_, 256>>>(1, g2, be2);
    k_mlp3<<<gmlp, 256, 18688 * 4>>>(W3, b3, Wih, bih, bhh);
    k_lstm_mm<<<NBLK, 256, LSTM_SMEM>>>(bih, bhh, out);
}

// round 5
// speedup vs baseline: 3.2238x; 1.6522x over previous
#include <cuda_runtime.h>
#include <cuda_bf16.h>
#include <cstdint>
#include <cstddef>

#define B_    32768
#define T_    3
#define D_    64
#define H_    32
#define NBLK  128   // B_/256

// ---------------- scratch (device globals: allocation-free) ----------------
__device__ float g_h1[(size_t)T_ * B_ * H_];
__device__ float g_h2[(size_t)T_ * B_ * H_];
__device__ unsigned long long g_xg[(size_t)T_ * 128 * B_]; // xg pairs [t][j/2][r]
__device__ float g_ps1[T_ * NBLK * H_];
__device__ float g_pq1[T_ * NBLK * H_];
__device__ float g_ps2[T_ * NBLK * H_];
__device__ float g_pq2[T_ * NBLK * H_];
__device__ float2 g_bn1[T_ * H_];   // (scale, shift)
__device__ float2 g_bn2[T_ * H_];
// weight tiles: 6 x [256 n][64 k] bf16, 128B rows, SW128-swizzled
// 0 = Whh_hi, 1 = Whh_lo, 2 = (Wih+Whh)_hi, 3 = (Wih+Whh)_lo, 4 = Wih_hi, 5 = Wih_lo
__device__ __align__(16) uint8_t g_wt[6 * 32768];

#define UNPK(v, lo, hi) do { unsigned _l, _h; \
    asm("mov.b64 {%0,%1}, %2;" : "=r"(_l), "=r"(_h) : "l"(v)); \
    lo = __uint_as_float(_l); hi = __uint_as_float(_h); } while (0)
#define PK64(lo, hi, v) asm("mov.b64 %0, {%1,%2};" : "=l"(v) : "r"(__float_as_uint(lo)), "r"(__float_as_uint(hi)))

__device__ __forceinline__ float ex2f(float x) {
    float r; asm("ex2.approx.ftz.f32 %0, %1;" : "=f"(r) : "f"(x)); return r;
}
__device__ __forceinline__ float rcpf(float x) {
    float r; asm("rcp.approx.ftz.f32 %0, %1;" : "=f"(r) : "f"(x)); return r;
}
// fused LSTM cell: cn = sig(f)c + sig(i)tanh(g); h = sig(o)tanh(cn). 7 MUFU total.
__device__ __forceinline__ void lstm_cell(float gi, float gf, float gg, float go,
                                          float& c, float& h) {
    const float L2E = 1.4426950408889634f;
    float a = ex2f(-L2E * gf);
    float u = ex2f(-L2E * gi);
    float b = ex2f(-2.f * L2E * gg);
    float pa = 1.f + a, pu = 1.f + u, pb = 1.f + b;
    float t1 = pu * pb;
    float cn = (c * t1 + (1.f - b) * pa) * rcpf(pa * t1);
    float v = ex2f(-L2E * go);
    float w = ex2f(-2.f * L2E * cn);
    c = cn;
    h = (1.f - w) * rcpf((1.f + v) * (1.f + w));
}
__host__ __device__ __forceinline__ uint32_t swz128(uint32_t o) {
    return o ^ ((o >> 3) & 0x70);
}

// ---------------- stage 1: h1 = x @ W1^T + b1, + batch partials ----------------
__global__ void __launch_bounds__(256) k_mlp1(const float* __restrict__ x,
                                              const float* __restrict__ W1,
                                              const float* __restrict__ b1) {
    __shared__ float sW[D_ * H_];
    __shared__ float sr0[8 * 32], sr1[8 * 32];
    int tid = threadIdx.x;
    int t = blockIdx.y;
    int r = blockIdx.x * 256 + tid;
    for (int i = tid; i < D_ * H_; i += 256) { int j = i >> 6, k = i & 63; sW[k * H_ + j] = W1[i]; }
    __syncthreads();

    float xr[64];
    const float4* xp = (const float4*)(x + ((size_t)t * B_ + r) * D_);
#pragma unroll
    for (int i = 0; i < 16; i++) {
        float4 v = xp[i];
        xr[4*i] = v.x; xr[4*i+1] = v.y; xr[4*i+2] = v.z; xr[4*i+3] = v.w;
    }
    float acc[32];
#pragma unroll
    for (int j = 0; j < 32; j++) acc[j] = __ldg(&b1[j]);
#pragma unroll
    for (int k = 0; k < 64; k++) {
        float xk = xr[k];
#pragma unroll
        for (int q = 0; q < 8; q++) {
            float4 w = *(const float4*)&sW[k * H_ + q * 4];
            acc[q*4+0] = fmaf(w.x, xk, acc[q*4+0]);
            acc[q*4+1] = fmaf(w.y, xk, acc[q*4+1]);
            acc[q*4+2] = fmaf(w.z, xk, acc[q*4+2]);
            acc[q*4+3] = fmaf(w.w, xk, acc[q*4+3]);
        }
    }
    float4* op = (float4*)(g_h1 + ((size_t)t * B_ + r) * H_);
#pragma unroll
    for (int q = 0; q < 8; q++) op[q] = make_float4(acc[q*4], acc[q*4+1], acc[q*4+2], acc[q*4+3]);

    int lane = tid & 31, wp = tid >> 5;
#pragma unroll
    for (int j = 0; j < 32; j++) {
        float s = acc[j], q = acc[j] * acc[j];
#pragma unroll
        for (int o = 16; o; o >>= 1) {
            s += __shfl_xor_sync(0xffffffffu, s, o);
            q += __shfl_xor_sync(0xffffffffu, q, o);
        }
        if (lane == 0) { sr0[wp * 32 + j] = s; sr1[wp * 32 + j] = q; }
    }
    __syncthreads();
    if (tid < 32) {
        float s = 0.f, q = 0.f;
#pragma unroll
        for (int w2 = 0; w2 < 8; w2++) { s += sr0[w2 * 32 + tid]; q += sr1[w2 * 32 + tid]; }
        g_ps1[(t * NBLK + blockIdx.x) * 32 + tid] = s;
        g_pq1[(t * NBLK + blockIdx.x) * 32 + tid] = q;
    }
}

// ---------------- BN stats reduce (parallel: 3 blocks x 256 thr) ----------------
__global__ void k_stats(int which, const float* __restrict__ gam, const float* __restrict__ bet) {
    __shared__ float ss[256], sq[256];
    int t = blockIdx.x;
    int tid = threadIdx.x;
    int ch = tid & 31, part = tid >> 5;
    const float* ps = which ? g_ps2 : g_ps1;
    const float* pq = which ? g_pq2 : g_pq1;
    float s = 0.f, q = 0.f;
#pragma unroll
    for (int b = 0; b < 16; b++) {
        int blk = part * 16 + b;
        s += ps[(t * NBLK + blk) * 32 + ch];
        q += pq[(t * NBLK + blk) * 32 + ch];
    }
    ss[tid] = s; sq[tid] = q;
    __syncthreads();
    if (tid < 32) {
#pragma unroll
        for (int p = 1; p < 8; p++) { s += ss[p * 32 + tid]; q += sq[p * 32 + tid]; }
        float m = s * (1.f / B_);
        float v = q * (1.f / B_) - m * m;
        float sc = gam[tid] * rsqrtf(v + 1e-5f);
        float2 o = make_float2(sc, bet[tid] - m * sc);
        if (which) g_bn2[t * 32 + tid] = o; else g_bn1[t * 32 + tid] = o;
    }
}

// ---------------- stage 2: h2 = relu(BN1(h1)) @ W2^T + b2, + partials ----------------
__global__ void __launch_bounds__(256) k_mlp2(const float* __restrict__ W2,
                                              const float* __restrict__ b2) {
    __shared__ float sW[H_ * H_];
    __shared__ float sr0[8 * 32], sr1[8 * 32];
    int tid = threadIdx.x;
    int t = blockIdx.y;
    int r = blockIdx.x * 256 + tid;
    for (int i = tid; i < H_ * H_; i += 256) { int j = i >> 5, k = i & 31; sW[k * H_ + j] = W2[i]; }
    __syncthreads();

    float a[32];
    const float4* hp = (const float4*)(g_h1 + ((size_t)t * B_ + r) * H_);
#pragma unroll
    for (int i = 0; i < 8; i++) {
        float4 v = hp[i];
        float2 s0 = g_bn1[t * 32 + i * 4 + 0]; a[i*4+0] = fmaxf(0.f, fmaf(v.x, s0.x, s0.y));
        float2 s1 = g_bn1[t * 32 + i * 4 + 1]; a[i*4+1] = fmaxf(0.f, fmaf(v.y, s1.x, s1.y));
        float2 s2 = g_bn1[t * 32 + i * 4 + 2]; a[i*4+2] = fmaxf(0.f, fmaf(v.z, s2.x, s2.y));
        float2 s3 = g_bn1[t * 32 + i * 4 + 3]; a[i*4+3] = fmaxf(0.f, fmaf(v.w, s3.x, s3.y));
    }
    float acc[32];
#pragma unroll
    for (int j = 0; j < 32; j++) acc[j] = __ldg(&b2[j]);
#pragma unroll
    for (int k = 0; k < 32; k++) {
        float ak = a[k];
#pragma unroll
        for (int q = 0; q < 8; q++) {
            float4 w = *(const float4*)&sW[k * H_ + q * 4];
            acc[q*4+0] = fmaf(w.x, ak, acc[q*4+0]);
            acc[q*4+1] = fmaf(w.y, ak, acc[q*4+1]);
            acc[q*4+2] = fmaf(w.z, ak, acc[q*4+2]);
            acc[q*4+3] = fmaf(w.w, ak, acc[q*4+3]);
        }
    }
    float4* op = (float4*)(g_h2 + ((size_t)t * B_ + r) * H_);
#pragma unroll
    for (int q = 0; q < 8; q++) op[q] = make_float4(acc[q*4], acc[q*4+1], acc[q*4+2], acc[q*4+3]);

    int lane = tid & 31, wp = tid >> 5;
#pragma unroll
    for (int j = 0; j < 32; j++) {
        float s = acc[j], q = acc[j] * acc[j];
#pragma unroll
        for (int o = 16; o; o >>= 1) {
            s += __shfl_xor_sync(0xffffffffu, s, o);
            q += __shfl_xor_sync(0xffffffffu, q, o);
        }
        if (lane == 0) { sr0[wp * 32 + j] = s; sr1[wp * 32 + j] = q; }
    }
    __syncthreads();
    if (tid < 32) {
        float s = 0.f, q = 0.f;
#pragma unroll
        for (int w2 = 0; w2 < 8; w2++) { s += sr0[w2 * 32 + tid]; q += sr1[w2 * 32 + tid]; }
        g_ps2[(t * NBLK + blockIdx.x) * 32 + tid] = s;
        g_pq2[(t * NBLK + blockIdx.x) * 32 + tid] = q;
    }
}

// ---------------- weight split/prep for HMMA tiles (parallel) ----------------
__global__ void k_prep(const float* __restrict__ Wih, const float* __restrict__ Whh) {
    int idx = blockIdx.x * 256 + threadIdx.x;   // 16384 total
    int n = idx >> 6, k = idx & 63;
    float whh = Whh[idx];
    float wih = Wih[idx];
    float ws = whh + wih;
    __nv_bfloat16 hh = __float2bfloat16_rn(whh);
    __nv_bfloat16 hl = __float2bfloat16_rn(whh - __bfloat162float(hh));
    __nv_bfloat16 sh = __float2bfloat16_rn(ws);
    __nv_bfloat16 sl = __float2bfloat16_rn(ws - __bfloat162float(sh));
    __nv_bfloat16 ih = __float2bfloat16_rn(wih);
    __nv_bfloat16 il = __float2bfloat16_rn(wih - __bfloat162float(ih));
    uint32_t off = swz128((uint32_t)(n * 128 + k * 2));
    *(__nv_bfloat16*)(g_wt + 0 * 32768 + off) = hh;
    *(__nv_bfloat16*)(g_wt + 1 * 32768 + off) = hl;
    *(__nv_bfloat16*)(g_wt + 2 * 32768 + off) = sh;
    *(__nv_bfloat16*)(g_wt + 3 * 32768 + off) = sl;
    *(__nv_bfloat16*)(g_wt + 4 * 32768 + off) = ih;
    *(__nv_bfloat16*)(g_wt + 5 * 32768 + off) = il;
}

// ---------------- HMMA helpers ----------------
__device__ __forceinline__ void mma_bf16(float d[4], const uint32_t a[4],
                                         uint32_t b0, uint32_t b1) {
    asm volatile(
        "mma.sync.aligned.m16n8k16.row.col.f32.bf16.bf16.f32 "
        "{%0,%1,%2,%3}, {%4,%5,%6,%7}, {%8,%9}, {%0,%1,%2,%3};"
        : "+f"(d[0]), "+f"(d[1]), "+f"(d[2]), "+f"(d[3])
        : "r"(a[0]), "r"(a[1]), "r"(a[2]), "r"(a[3]), "r"(b0), "r"(b1));
}
__device__ __forceinline__ void ldsm4(uint32_t r[4], uint32_t addr) {
    asm volatile("ldmatrix.sync.aligned.m8n8.x4.shared.b16 {%0,%1,%2,%3}, [%4];"
                 : "=r"(r[0]), "=r"(r[1]), "=r"(r[2]), "=r"(r[3]) : "r"(addr) : "memory");
}
__device__ __forceinline__ uint32_t pack_bf16(float lo, float hi) {
    uint32_t r;
    asm("cvt.rn.bf16x2.f32 %0, %1, %2;" : "=r"(r) : "f"(hi), "f"(lo));
    return r;
}

// ---- stage 3: enc = relu(BN2(h2)) @ W3^T + b3; xg = enc @ Wih^T + bsum (HMMA) ----
// smem: A enc tiles hi@0 lo@32768 (64KB), Wih hi@65536 lo@98304 (64KB),
//       sW3 @131072 (8KB), sb @139264 (1KB)
#define M3_AHI 0u
#define M3_ALO 32768u
#define M3_WHI 65536u
#define M3_SW3 131072u
#define M3_SB  139264u
#define M3_SMEM 140288
__global__ void __launch_bounds__(256) k_mlp3(const float* __restrict__ W3,
                                              const float* __restrict__ b3,
                                              const float* __restrict__ bih,
                                              const float* __restrict__ bhh) {
    extern __shared__ __align__(16) uint8_t sm3[];
    uint32_t smem_base;
    asm("{ .reg .u64 t; cvta.to.shared.u64 t, %1; cvt.u32.u64 %0, t; }"
        : "=r"(smem_base) : "l"(sm3));
    float* sW3 = (float*)(sm3 + M3_SW3);
    float* sb  = (float*)(sm3 + M3_SB);
    const int tid = threadIdx.x, wid = tid >> 5, lane = tid & 31;
    const int t = blockIdx.y;

    for (int i = tid; i < 2048; i += 256) { int j = i >> 5, k = i & 31; sW3[k * 64 + j] = W3[i]; }
    {   // Wih hi/lo tiles
        const uint4* src = (const uint4*)(g_wt + 4 * 32768);
        uint4* dst = (uint4*)(sm3 + M3_WHI);
        for (int i = tid; i < 65536 / 16; i += 256) dst[i] = src[i];
    }
    sb[tid] = bih[tid] + bhh[tid];
    __syncthreads();

    // phase 1: enc for own row (= tid)
    const size_t r = (size_t)blockIdx.x * 256 + tid;
    float a[32];
    const float4* hp = (const float4*)(g_h2 + ((size_t)t * B_ + r) * H_);
#pragma unroll
    for (int i = 0; i < 8; i++) {
        float4 v = hp[i];
        float2 s0 = g_bn2[t * 32 + i * 4 + 0]; a[i*4+0] = fmaxf(0.f, fmaf(v.x, s0.x, s0.y));
        float2 s1 = g_bn2[t * 32 + i * 4 + 1]; a[i*4+1] = fmaxf(0.f, fmaf(v.y, s1.x, s1.y));
        float2 s2 = g_bn2[t * 32 + i * 4 + 2]; a[i*4+2] = fmaxf(0.f, fmaf(v.z, s2.x, s2.y));
        float2 s3 = g_bn2[t * 32 + i * 4 + 3]; a[i*4+3] = fmaxf(0.f, fmaf(v.w, s3.x, s3.y));
    }
    float e[64];
#pragma unroll
    for (int j = 0; j < 64; j++) e[j] = __ldg(&b3[j]);
#pragma unroll
    for (int k = 0; k < 32; k++) {
        float ak = a[k];
#pragma unroll
        for (int q = 0; q < 16; q++) {
            float4 w = *(const float4*)&sW3[k * 64 + q * 4];
            e[q*4+0] = fmaf(w.x, ak, e[q*4+0]);
            e[q*4+1] = fmaf(w.y, ak, e[q*4+1]);
            e[q*4+2] = fmaf(w.z, ak, e[q*4+2]);
            e[q*4+3] = fmaf(w.w, ak, e[q*4+3]);
        }
    }
    // split enc -> bf16 hi/lo A tiles (row = tid, SW128)
    {
        const uint32_t rb = (uint32_t)tid * 128u;
        const uint32_t rx = (uint32_t)(tid & 7) * 16u;
#pragma unroll
        for (int q = 0; q < 8; q++) {
            uint32_t off = rb + (((uint32_t)q * 16u) ^ rx);
            uint32_t ph[4], pl[4];
#pragma unroll
            for (int j = 0; j < 4; j++) {
                float e0 = e[q*8 + 2*j], e1 = e[q*8 + 2*j + 1];
                uint32_t p = pack_bf16(e0, e1);
                ph[j] = p;
                pl[j] = pack_bf16(e0 - __uint_as_float(p << 16),
                                  e1 - __uint_as_float(p & 0xffff0000u));
            }
            *(uint4*)(sm3 + M3_AHI + off) = make_uint4(ph[0], ph[1], ph[2], ph[3]);
            *(uint4*)(sm3 + M3_ALO + off) = make_uint4(pl[0], pl[1], pl[2], pl[3]);
        }
    }
    __syncwarp();

    // phase 2: xg = enc @ Wih^T + bsum via HMMA (warp-private rows)
    const int l7 = lane & 7;
    const uint32_t lxor = (uint32_t)l7 * 16u;
    const uint32_t aoff16 = (uint32_t)((lane >> 4) & 1) * 16u;
    const uint32_t boff16 = (uint32_t)((lane >> 3) & 1) * 16u;
    const uint32_t arow0 = (uint32_t)(wid * 32 + l7 + ((lane >> 3) & 1) * 8) * 128u;
    const uint32_t brow_l = (uint32_t)(((lane >> 4) & 1) * 8 + l7) * 128u;
    const int qr = lane >> 2, qc = lane & 3;
    const size_t rowG0 = (size_t)blockIdx.x * 256 + wid * 32 + qr;
    const uint32_t aHi = smem_base + M3_AHI, aLo = smem_base + M3_ALO;
    const uint32_t whi = smem_base + M3_WHI;
    unsigned long long* xgt = g_xg + (size_t)t * 128 * B_;

#pragma unroll
    for (int cd = 0; cd < 4; cd++) {
        float acc[2][4][2][4];
#pragma unroll
        for (int mt = 0; mt < 2; mt++)
#pragma unroll
            for (int g = 0; g < 4; g++)
#pragma unroll
                for (int ds = 0; ds < 2; ds++)
#pragma unroll
                    for (int z = 0; z < 4; z++) acc[mt][g][ds][z] = 0.f;
        const uint32_t brow_cd = (uint32_t)(cd * 16) * 128u + brow_l;
#pragma unroll
        for (int kt = 0; kt < 4; kt++) {
            const uint32_t acol = ((uint32_t)(kt * 32) + aoff16) ^ lxor;
            const uint32_t bcol = ((uint32_t)(kt * 32) + boff16) ^ lxor;
            uint32_t ah[2][4], al[2][4];
            ldsm4(ah[0], aHi + arow0 + acol);
            ldsm4(ah[1], aHi + arow0 + 2048u + acol);
            ldsm4(al[0], aLo + arow0 + acol);
            ldsm4(al[1], aLo + arow0 + 2048u + acol);
            uint32_t bh[4][4], bl[4][4];
#pragma unroll
            for (int g = 0; g < 4; g++) {
                ldsm4(bh[g], whi + (uint32_t)g * 8192u + brow_cd + bcol);
                ldsm4(bl[g], whi + 32768u + (uint32_t)g * 8192u + brow_cd + bcol);
            }
#pragma unroll
            for (int mt = 0; mt < 2; mt++)
#pragma unroll
                for (int g = 0; g < 4; g++)
#pragma unroll
                    for (int ds = 0; ds < 2; ds++) {
                        mma_bf16(acc[mt][g][ds], ah[mt], bh[g][ds*2], bh[g][ds*2+1]);
                        mma_bf16(acc[mt][g][ds], al[mt], bh[g][ds*2], bh[g][ds*2+1]);
                        mma_bf16(acc[mt][g][ds], ah[mt], bl[g][ds*2], bl[g][ds*2+1]);
                    }
        }
        // add bsum, store fp32 pairs to xg
#pragma unroll
        for (int g = 0; g < 4; g++)
#pragma unroll
            for (int ds = 0; ds < 2; ds++) {
                const int pi = cd * 8 + ds * 4 + qc;
                float2 bs = *(const float2*)&sb[g * 64 + 2 * pi];
#pragma unroll
                for (int mt = 0; mt < 2; mt++)
#pragma unroll
                    for (int rr = 0; rr < 2; rr++) {
                        float v0 = acc[mt][g][ds][rr*2]     + bs.x;
                        float v1 = acc[mt][g][ds][rr*2 + 1] + bs.y;
                        unsigned long long pk;
                        PK64(v0, v1, pk);
                        xgt[(size_t)(g * 32 + pi) * B_ + rowG0 + mt * 16 + rr * 8] = pk;
                    }
            }
    }
}

// smem layout (bytes): A buffers 2x(hi 32K + lo 32K) @0..131072,
// W_hi @131072, W_lo @163840, bsum @196608
#define SW_OFF   131072u
#define SBIAS    196608u
#define LSTM_SMEM 197632

// ---------------- stage 4: HMMA 28-step LSTM, 256 rows/CTA, warp-private ----------------
__global__ void __launch_bounds__(256, 1) k_lstm_mm(const float* __restrict__ bih,
                                                    const float* __restrict__ bhh,
                                                    float* __restrict__ out) {
    extern __shared__ __align__(16) uint8_t sm[];
    uint32_t smem_base;
    asm("{ .reg .u64 t; cvta.to.shared.u64 t, %1; cvt.u32.u64 %0, t; }"
        : "=r"(smem_base) : "l"(sm));
    float* sbsum = (float*)(sm + SBIAS);
    const int tid = threadIdx.x, wid = tid >> 5, lane = tid & 31;

    {   // Whh hi/lo tiles + biases
        const uint4* src = (const uint4*)g_wt;
        uint4* dst = (uint4*)(sm + SW_OFF);
        for (int i = tid; i < 65536 / 16; i += 256) dst[i] = src[i];
        sbsum[tid] = bih[tid] + bhh[tid];
    }
    __syncthreads();

    const int l7 = lane & 7;
    const uint32_t lxor = (uint32_t)l7 * 16u;
    const uint32_t aoff16 = (uint32_t)((lane >> 4) & 1) * 16u;
    const uint32_t boff16 = (uint32_t)((lane >> 3) & 1) * 16u;
    const uint32_t arow0 = (uint32_t)(wid * 32 + l7 + ((lane >> 3) & 1) * 8) * 128u;
    const uint32_t brow_l = (uint32_t)(((lane >> 4) & 1) * 8 + l7) * 128u;
    const int qr = lane >> 2, qc = lane & 3;
    const int rowL0 = wid * 32 + qr;
    const size_t rowG0 = (size_t)blockIdx.x * 256 + rowL0;

    float c[64];
#pragma unroll
    for (int i = 0; i < 64; i++) c[i] = 0.f;

#pragma unroll 1
    for (int s = 0; s < 28; s++) {
        if (s == 4) {  // swap weights: Whh -> Wih+Whh
            __syncthreads();
            const uint4* src = (const uint4*)(g_wt + 65536);
            uint4* dst = (uint4*)(sm + SW_OFF);
            for (int i = tid; i < 65536 / 16; i += 256) dst[i] = src[i];
            __syncthreads();
        }
        const uint32_t aRd = smem_base + (uint32_t)((s + 1) & 1) * 65536u;
        uint8_t* aWr = sm + (uint32_t)(s & 1) * 65536u;
        const uint32_t whi = smem_base + SW_OFF;
        const int tsel = (s < 3) ? s : 2;
        const unsigned long long* xbase = g_xg + (size_t)tsel * 128 * B_;

#pragma unroll
        for (int cd = 0; cd < 4; cd++) {
            float acc[2][4][2][4];
#pragma unroll
            for (int mt = 0; mt < 2; mt++)
#pragma unroll
                for (int g = 0; g < 4; g++)
#pragma unroll
                    for (int ds = 0; ds < 2; ds++)
#pragma unroll
                        for (int z = 0; z < 4; z++) acc[mt][g][ds][z] = 0.f;

            if (s >= 1) {
                const uint32_t brow_cd = (uint32_t)(cd * 16) * 128u + brow_l;
#pragma unroll
                for (int kt = 0; kt < 4; kt++) {
                    const uint32_t acol = ((uint32_t)(kt * 32) + aoff16) ^ lxor;
                    const uint32_t bcol = ((uint32_t)(kt * 32) + boff16) ^ lxor;
                    uint32_t ah[2][4], al[2][4];
                    ldsm4(ah[0], aRd + arow0 + acol);
                    ldsm4(ah[1], aRd + arow0 + 2048u + acol);
                    ldsm4(al[0], aRd + 32768u + arow0 + acol);
                    ldsm4(al[1], aRd + 32768u + arow0 + 2048u + acol);
                    uint32_t bh[4][4], bl[4][4];
#pragma unroll
                    for (int g = 0; g < 4; g++) {
                        ldsm4(bh[g], whi + (uint32_t)g * 8192u + brow_cd + bcol);
                        ldsm4(bl[g], whi + 32768u + (uint32_t)g * 8192u + brow_cd + bcol);
                    }
#pragma unroll
                    for (int mt = 0; mt < 2; mt++)
#pragma unroll
                        for (int g = 0; g < 4; g++)
#pragma unroll
                            for (int ds = 0; ds < 2; ds++) {
                                mma_bf16(acc[mt][g][ds], ah[mt], bh[g][ds*2], bh[g][ds*2+1]);
                                mma_bf16(acc[mt][g][ds], al[mt], bh[g][ds*2], bh[g][ds*2+1]);
                                mma_bf16(acc[mt][g][ds], ah[mt], bl[g][ds*2], bl[g][ds*2+1]);
                            }
                }
            }

            // epilogue for this 16-d chunk
            const int pbase = cd * 8 + qc;
#pragma unroll
            for (int mt = 0; mt < 2; mt++)
#pragma unroll
                for (int ds = 0; ds < 2; ds++) {
                    const int dbase = cd * 16 + ds * 8 + 2 * qc;
                    float2 bi, bf, bg, bo;
                    if (s >= 4) {
                        bi = *(const float2*)&sbsum[0 * 64 + dbase];
                        bf = *(const float2*)&sbsum[1 * 64 + dbase];
                        bg = *(const float2*)&sbsum[2 * 64 + dbase];
                        bo = *(const float2*)&sbsum[3 * 64 + dbase];
                    }
#pragma unroll
                    for (int rr = 0; rr < 2; rr++) {
                        const int rowL = rowL0 + mt * 16 + rr * 8;
                        float gi0 = acc[mt][0][ds][rr*2], gi1 = acc[mt][0][ds][rr*2+1];
                        float gf0 = acc[mt][1][ds][rr*2], gf1 = acc[mt][1][ds][rr*2+1];
                        float gg0 = acc[mt][2][ds][rr*2], gg1 = acc[mt][2][ds][rr*2+1];
                        float go0 = acc[mt][3][ds][rr*2], go1 = acc[mt][3][ds][rr*2+1];
                        if (s < 4) {
                            const unsigned long long* xp = xbase + (rowG0 + mt * 16 + rr * 8);
                            const int pi = pbase + ds * 4;
                            float lo, hi;
                            unsigned long long v;
                            v = xp[(size_t)(0 * 32 + pi) * B_]; UNPK(v, lo, hi); gi0 += lo; gi1 += hi;
                            v = xp[(size_t)(1 * 32 + pi) * B_]; UNPK(v, lo, hi); gf0 += lo; gf1 += hi;
                            v = xp[(size_t)(2 * 32 + pi) * B_]; UNPK(v, lo, hi); gg0 += lo; gg1 += hi;
                            v = xp[(size_t)(3 * 32 + pi) * B_]; UNPK(v, lo, hi); go0 += lo; go1 += hi;
                        } else {
                            gi0 += bi.x; gi1 += bi.y;
                            gf0 += bf.x; gf1 += bf.y;
                            gg0 += bg.x; gg1 += bg.y;
                            go0 += bo.x; go1 += bo.y;
                        }
                        const int ci = (((cd * 2 + ds) * 2 + mt) * 2 + rr) * 2;
                        float h0, h1;
                        lstm_cell(gi0, gf0, gg0, go0, c[ci], h0);
                        lstm_cell(gi1, gf1, gg1, go1, c[ci + 1], h1);
                        // split h into bf16 hi/lo and store to next-step A tile
                        uint32_t ph = pack_bf16(h0, h1);
                        float e0 = h0 - __uint_as_float(ph << 16);
                        float e1 = h1 - __uint_as_float(ph & 0xffff0000u);
                        uint32_t pl = pack_bf16(e0, e1);
                        uint32_t soff = (uint32_t)rowL * 128u +
                                        (((uint32_t)(cd * 32 + ds * 16 + qc * 4)) ^ ((uint32_t)qr * 16u));
                        *(uint32_t*)(aWr + soff) = ph;
                        *(uint32_t*)(aWr + 32768u + soff) = pl;
                        if (s >= 3) {
                            float2 o2 = make_float2(h0, h1);
                            *(float2*)(out + ((rowG0 + mt * 16 + rr * 8) * 25 + (s - 3)) * 64 + dbase) = o2;
                        }
                    }
                }
        }
        __syncwarp();
    }
}

// ---------------- host ----------------
extern "C" void kernel_launch(void* const* d_in, const int* in_sizes, int n_in,
                              void* d_out, int out_size) {
    const float* x   = (const float*)d_in[0];
    const float* W1  = (const float*)d_in[1];
    const float* b1  = (const float*)d_in[2];
    const float* g1  = (const float*)d_in[3];
    const float* be1 = (const float*)d_in[4];
    const float* W2  = (const float*)d_in[5];
    const float* b2  = (const float*)d_in[6];
    const float* g2  = (const float*)d_in[7];
    const float* be2 = (const float*)d_in[8];
    const float* W3  = (const float*)d_in[9];
    const float* b3  = (const float*)d_in[10];
    const float* Wih = (const float*)d_in[11];
    const float* Whh = (const float*)d_in[12];
    const float* bih = (const float*)d_in[13];
    const float* bhh = (const float*)d_in[14];
    float* out = (float*)d_out;

    static bool attr_done = false;
    if (!attr_done) {
        cudaFuncSetAttribute(k_mlp3, cudaFuncAttributeMaxDynamicSharedMemorySize, M3_SMEM);
        cudaFuncSetAttribute(k_lstm_mm, cudaFuncAttributeMaxDynamicSharedMemorySize, LSTM_SMEM);
        attr_done = true;
    }

    dim3 gmlp(NBLK, T_);
    k_prep<<<64, 256>>>(Wih, Whh);
    k_mlp1<<<gmlp, 256>>>(x, W1, b1);
    k_stats<<<T_, 256>>>(0, g1, be1);
    k_mlp2<<<gmlp, 256>>>(W2, b2);
    k_stats<<<T_, 256>>>(1, g2, be2);
    k_mlp3<<<gmlp, 256, M3_SMEM>>>(W3, b3, bih, bhh);
    k_lstm_mm<<<NBLK, 256, LSTM_SMEM>>>(bih, bhh, out);
}

// round 6
// speedup vs baseline: 3.6328x; 1.1269x over previous
#include <cuda_runtime.h>
#include <cuda_bf16.h>
#include <cstdint>
#include <cstddef>

#define B_    32768
#define T_    3
#define D_    64
#define H_    32
#define NBLK  128   // B_/256

// ---------------- scratch (device globals: allocation-free) ----------------
__device__ float g_h1[(size_t)T_ * B_ * H_];
__device__ float g_h2[(size_t)T_ * B_ * H_];
__device__ unsigned long long g_xg[(size_t)T_ * 128 * B_]; // xg pairs [t][j/2][r]
__device__ float g_ps1[T_ * NBLK * H_];
__device__ float g_pq1[T_ * NBLK * H_];
__device__ float g_ps2[T_ * NBLK * H_];
__device__ float g_pq2[T_ * NBLK * H_];
__device__ float2 g_bn1[T_ * H_];   // (scale, shift)
__device__ float2 g_bn2[T_ * H_];
// weight tiles: 6 x [256 n][64 k] bf16, 128B rows, SW128-swizzled
// 0 = Whh_hi, 1 = Whh_lo, 2 = (Wih+Whh)_hi, 3 = (Wih+Whh)_lo, 4 = Wih_hi, 5 = Wih_lo
__device__ __align__(16) uint8_t g_wt[6 * 32768];

#define UNPK(v, lo, hi) do { unsigned _l, _h; \
    asm("mov.b64 {%0,%1}, %2;" : "=r"(_l), "=r"(_h) : "l"(v)); \
    lo = __uint_as_float(_l); hi = __uint_as_float(_h); } while (0)
#define PK64(lo, hi, v) asm("mov.b64 %0, {%1,%2};" : "=l"(v) : "r"(__float_as_uint(lo)), "r"(__float_as_uint(hi)))

__device__ __forceinline__ float ex2f(float x) {
    float r; asm("ex2.approx.ftz.f32 %0, %1;" : "=f"(r) : "f"(x)); return r;
}
__device__ __forceinline__ float rcpf(float x) {
    float r; asm("rcp.approx.ftz.f32 %0, %1;" : "=f"(r) : "f"(x)); return r;
}
// fused LSTM cell: cn = sig(f)c + sig(i)tanh(g); h = sig(o)tanh(cn). 7 MUFU total.
__device__ __forceinline__ void lstm_cell(float gi, float gf, float gg, float go,
                                          float& c, float& h) {
    const float L2E = 1.4426950408889634f;
    float a = ex2f(-L2E * gf);
    float u = ex2f(-L2E * gi);
    float b = ex2f(-2.f * L2E * gg);
    float pa = 1.f + a, pu = 1.f + u, pb = 1.f + b;
    float t1 = pu * pb;
    float cn = (c * t1 + (1.f - b) * pa) * rcpf(pa * t1);
    float v = ex2f(-L2E * go);
    float w = ex2f(-2.f * L2E * cn);
    c = cn;
    h = (1.f - w) * rcpf((1.f + v) * (1.f + w));
}
__host__ __device__ __forceinline__ uint32_t swz128(uint32_t o) {
    return o ^ ((o >> 3) & 0x70);
}

// ---------------- stage 1: h1 = x @ W1^T + b1, + batch partials ----------------
__global__ void __launch_bounds__(256) k_mlp1(const float* __restrict__ x,
                                              const float* __restrict__ W1,
                                              const float* __restrict__ b1) {
    __shared__ float sW[D_ * H_];
    __shared__ float sr0[8 * 32], sr1[8 * 32];
    int tid = threadIdx.x;
    int t = blockIdx.y;
    int r = blockIdx.x * 256 + tid;
    for (int i = tid; i < D_ * H_; i += 256) { int j = i >> 6, k = i & 63; sW[k * H_ + j] = W1[i]; }
    __syncthreads();

    float xr[64];
    const float4* xp = (const float4*)(x + ((size_t)t * B_ + r) * D_);
#pragma unroll
    for (int i = 0; i < 16; i++) {
        float4 v = xp[i];
        xr[4*i] = v.x; xr[4*i+1] = v.y; xr[4*i+2] = v.z; xr[4*i+3] = v.w;
    }
    float acc[32];
#pragma unroll
    for (int j = 0; j < 32; j++) acc[j] = __ldg(&b1[j]);
#pragma unroll
    for (int k = 0; k < 64; k++) {
        float xk = xr[k];
#pragma unroll
        for (int q = 0; q < 8; q++) {
            float4 w = *(const float4*)&sW[k * H_ + q * 4];
            acc[q*4+0] = fmaf(w.x, xk, acc[q*4+0]);
            acc[q*4+1] = fmaf(w.y, xk, acc[q*4+1]);
            acc[q*4+2] = fmaf(w.z, xk, acc[q*4+2]);
            acc[q*4+3] = fmaf(w.w, xk, acc[q*4+3]);
        }
    }
    float4* op = (float4*)(g_h1 + ((size_t)t * B_ + r) * H_);
#pragma unroll
    for (int q = 0; q < 8; q++) op[q] = make_float4(acc[q*4], acc[q*4+1], acc[q*4+2], acc[q*4+3]);

    int lane = tid & 31, wp = tid >> 5;
#pragma unroll
    for (int j = 0; j < 32; j++) {
        float s = acc[j], q = acc[j] * acc[j];
#pragma unroll
        for (int o = 16; o; o >>= 1) {
            s += __shfl_xor_sync(0xffffffffu, s, o);
            q += __shfl_xor_sync(0xffffffffu, q, o);
        }
        if (lane == 0) { sr0[wp * 32 + j] = s; sr1[wp * 32 + j] = q; }
    }
    __syncthreads();
    if (tid < 32) {
        float s = 0.f, q = 0.f;
#pragma unroll
        for (int w2 = 0; w2 < 8; w2++) { s += sr0[w2 * 32 + tid]; q += sr1[w2 * 32 + tid]; }
        g_ps1[(t * NBLK + blockIdx.x) * 32 + tid] = s;
        g_pq1[(t * NBLK + blockIdx.x) * 32 + tid] = q;
    }
}

// ---------------- BN stats reduce (parallel: 3 blocks x 256 thr) ----------------
__global__ void k_stats(int which, const float* __restrict__ gam, const float* __restrict__ bet) {
    __shared__ float ss[256], sq[256];
    int t = blockIdx.x;
    int tid = threadIdx.x;
    int ch = tid & 31, part = tid >> 5;
    const float* ps = which ? g_ps2 : g_ps1;
    const float* pq = which ? g_pq2 : g_pq1;
    float s = 0.f, q = 0.f;
#pragma unroll
    for (int b = 0; b < 16; b++) {
        int blk = part * 16 + b;
        s += ps[(t * NBLK + blk) * 32 + ch];
        q += pq[(t * NBLK + blk) * 32 + ch];
    }
    ss[tid] = s; sq[tid] = q;
    __syncthreads();
    if (tid < 32) {
#pragma unroll
        for (int p = 1; p < 8; p++) { s += ss[p * 32 + tid]; q += sq[p * 32 + tid]; }
        float m = s * (1.f / B_);
        float v = q * (1.f / B_) - m * m;
        float sc = gam[tid] * rsqrtf(v + 1e-5f);
        float2 o = make_float2(sc, bet[tid] - m * sc);
        if (which) g_bn2[t * 32 + tid] = o; else g_bn1[t * 32 + tid] = o;
    }
}

// ---------------- stage 2: h2 = relu(BN1(h1)) @ W2^T + b2, + partials ----------------
__global__ void __launch_bounds__(256) k_mlp2(const float* __restrict__ W2,
                                              const float* __restrict__ b2) {
    __shared__ float sW[H_ * H_];
    __shared__ float sr0[8 * 32], sr1[8 * 32];
    int tid = threadIdx.x;
    int t = blockIdx.y;
    int r = blockIdx.x * 256 + tid;
    for (int i = tid; i < H_ * H_; i += 256) { int j = i >> 5, k = i & 31; sW[k * H_ + j] = W2[i]; }
    __syncthreads();

    float a[32];
    const float4* hp = (const float4*)(g_h1 + ((size_t)t * B_ + r) * H_);
#pragma unroll
    for (int i = 0; i < 8; i++) {
        float4 v = hp[i];
        float2 s0 = g_bn1[t * 32 + i * 4 + 0]; a[i*4+0] = fmaxf(0.f, fmaf(v.x, s0.x, s0.y));
        float2 s1 = g_bn1[t * 32 + i * 4 + 1]; a[i*4+1] = fmaxf(0.f, fmaf(v.y, s1.x, s1.y));
        float2 s2 = g_bn1[t * 32 + i * 4 + 2]; a[i*4+2] = fmaxf(0.f, fmaf(v.z, s2.x, s2.y));
        float2 s3 = g_bn1[t * 32 + i * 4 + 3]; a[i*4+3] = fmaxf(0.f, fmaf(v.w, s3.x, s3.y));
    }
    float acc[32];
#pragma unroll
    for (int j = 0; j < 32; j++) acc[j] = __ldg(&b2[j]);
#pragma unroll
    for (int k = 0; k < 32; k++) {
        float ak = a[k];
#pragma unroll
        for (int q = 0; q < 8; q++) {
            float4 w = *(const float4*)&sW[k * H_ + q * 4];
            acc[q*4+0] = fmaf(w.x, ak, acc[q*4+0]);
            acc[q*4+1] = fmaf(w.y, ak, acc[q*4+1]);
            acc[q*4+2] = fmaf(w.z, ak, acc[q*4+2]);
            acc[q*4+3] = fmaf(w.w, ak, acc[q*4+3]);
        }
    }
    float4* op = (float4*)(g_h2 + ((size_t)t * B_ + r) * H_);
#pragma unroll
    for (int q = 0; q < 8; q++) op[q] = make_float4(acc[q*4], acc[q*4+1], acc[q*4+2], acc[q*4+3]);

    int lane = tid & 31, wp = tid >> 5;
#pragma unroll
    for (int j = 0; j < 32; j++) {
        float s = acc[j], q = acc[j] * acc[j];
#pragma unroll
        for (int o = 16; o; o >>= 1) {
            s += __shfl_xor_sync(0xffffffffu, s, o);
            q += __shfl_xor_sync(0xffffffffu, q, o);
        }
        if (lane == 0) { sr0[wp * 32 + j] = s; sr1[wp * 32 + j] = q; }
    }
    __syncthreads();
    if (tid < 32) {
        float s = 0.f, q = 0.f;
#pragma unroll
        for (int w2 = 0; w2 < 8; w2++) { s += sr0[w2 * 32 + tid]; q += sr1[w2 * 32 + tid]; }
        g_ps2[(t * NBLK + blockIdx.x) * 32 + tid] = s;
        g_pq2[(t * NBLK + blockIdx.x) * 32 + tid] = q;
    }
}

// ---------------- weight split/prep for HMMA tiles (parallel) ----------------
__global__ void k_prep(const float* __restrict__ Wih, const float* __restrict__ Whh) {
    int idx = blockIdx.x * 256 + threadIdx.x;   // 16384 total
    int n = idx >> 6, k = idx & 63;
    float whh = Whh[idx];
    float wih = Wih[idx];
    float ws = whh + wih;
    __nv_bfloat16 hh = __float2bfloat16_rn(whh);
    __nv_bfloat16 hl = __float2bfloat16_rn(whh - __bfloat162float(hh));
    __nv_bfloat16 sh = __float2bfloat16_rn(ws);
    __nv_bfloat16 sl = __float2bfloat16_rn(ws - __bfloat162float(sh));
    __nv_bfloat16 ih = __float2bfloat16_rn(wih);
    __nv_bfloat16 il = __float2bfloat16_rn(wih - __bfloat162float(ih));
    uint32_t off = swz128((uint32_t)(n * 128 + k * 2));
    *(__nv_bfloat16*)(g_wt + 0 * 32768 + off) = hh;
    *(__nv_bfloat16*)(g_wt + 1 * 32768 + off) = hl;
    *(__nv_bfloat16*)(g_wt + 2 * 32768 + off) = sh;
    *(__nv_bfloat16*)(g_wt + 3 * 32768 + off) = sl;
    *(__nv_bfloat16*)(g_wt + 4 * 32768 + off) = ih;
    *(__nv_bfloat16*)(g_wt + 5 * 32768 + off) = il;
}

// ---------------- HMMA helpers ----------------
__device__ __forceinline__ void mma_bf16(float d[4], const uint32_t a[4],
                                         uint32_t b0, uint32_t b1) {
    asm volatile(
        "mma.sync.aligned.m16n8k16.row.col.f32.bf16.bf16.f32 "
        "{%0,%1,%2,%3}, {%4,%5,%6,%7}, {%8,%9}, {%0,%1,%2,%3};"
        : "+f"(d[0]), "+f"(d[1]), "+f"(d[2]), "+f"(d[3])
        : "r"(a[0]), "r"(a[1]), "r"(a[2]), "r"(a[3]), "r"(b0), "r"(b1));
}
__device__ __forceinline__ void ldsm4(uint32_t r[4], uint32_t addr) {
    asm volatile("ldmatrix.sync.aligned.m8n8.x4.shared.b16 {%0,%1,%2,%3}, [%4];"
                 : "=r"(r[0]), "=r"(r[1]), "=r"(r[2]), "=r"(r[3]) : "r"(addr) : "memory");
}
__device__ __forceinline__ uint32_t pack_bf16(float lo, float hi) {
    uint32_t r;
    asm("cvt.rn.bf16x2.f32 %0, %1, %2;" : "=r"(r) : "f"(hi), "f"(lo));
    return r;
}

// ---- stage 3: enc = relu(BN2(h2)) @ W3^T + b3; xg = enc @ Wih^T + bsum (HMMA) ----
#define M3_AHI 0u
#define M3_ALO 32768u
#define M3_WHI 65536u
#define M3_SW3 131072u
#define M3_SB  139264u
#define M3_SMEM 140288
__global__ void __launch_bounds__(256) k_mlp3(const float* __restrict__ W3,
                                              const float* __restrict__ b3,
                                              const float* __restrict__ bih,
                                              const float* __restrict__ bhh) {
    extern __shared__ __align__(16) uint8_t sm3[];
    uint32_t smem_base;
    asm("{ .reg .u64 t; cvta.to.shared.u64 t, %1; cvt.u32.u64 %0, t; }"
        : "=r"(smem_base) : "l"(sm3));
    float* sW3 = (float*)(sm3 + M3_SW3);
    float* sb  = (float*)(sm3 + M3_SB);
    const int tid = threadIdx.x, wid = tid >> 5, lane = tid & 31;
    const int t = blockIdx.y;

    for (int i = tid; i < 2048; i += 256) { int j = i >> 5, k = i & 31; sW3[k * 64 + j] = W3[i]; }
    {
        const uint4* src = (const uint4*)(g_wt + 4 * 32768);
        uint4* dst = (uint4*)(sm3 + M3_WHI);
        for (int i = tid; i < 65536 / 16; i += 256) dst[i] = src[i];
    }
    sb[tid] = bih[tid] + bhh[tid];
    __syncthreads();

    const size_t r = (size_t)blockIdx.x * 256 + tid;
    float a[32];
    const float4* hp = (const float4*)(g_h2 + ((size_t)t * B_ + r) * H_);
#pragma unroll
    for (int i = 0; i < 8; i++) {
        float4 v = hp[i];
        float2 s0 = g_bn2[t * 32 + i * 4 + 0]; a[i*4+0] = fmaxf(0.f, fmaf(v.x, s0.x, s0.y));
        float2 s1 = g_bn2[t * 32 + i * 4 + 1]; a[i*4+1] = fmaxf(0.f, fmaf(v.y, s1.x, s1.y));
        float2 s2 = g_bn2[t * 32 + i * 4 + 2]; a[i*4+2] = fmaxf(0.f, fmaf(v.z, s2.x, s2.y));
        float2 s3 = g_bn2[t * 32 + i * 4 + 3]; a[i*4+3] = fmaxf(0.f, fmaf(v.w, s3.x, s3.y));
    }
    float e[64];
#pragma unroll
    for (int j = 0; j < 64; j++) e[j] = __ldg(&b3[j]);
#pragma unroll
    for (int k = 0; k < 32; k++) {
        float ak = a[k];
#pragma unroll
        for (int q = 0; q < 16; q++) {
            float4 w = *(const float4*)&sW3[k * 64 + q * 4];
            e[q*4+0] = fmaf(w.x, ak, e[q*4+0]);
            e[q*4+1] = fmaf(w.y, ak, e[q*4+1]);
            e[q*4+2] = fmaf(w.z, ak, e[q*4+2]);
            e[q*4+3] = fmaf(w.w, ak, e[q*4+3]);
        }
    }
    {
        const uint32_t rb = (uint32_t)tid * 128u;
        const uint32_t rx = (uint32_t)(tid & 7) * 16u;
#pragma unroll
        for (int q = 0; q < 8; q++) {
            uint32_t off = rb + (((uint32_t)q * 16u) ^ rx);
            uint32_t ph[4], pl[4];
#pragma unroll
            for (int j = 0; j < 4; j++) {
                float e0 = e[q*8 + 2*j], e1 = e[q*8 + 2*j + 1];
                uint32_t p = pack_bf16(e0, e1);
                ph[j] = p;
                pl[j] = pack_bf16(e0 - __uint_as_float(p << 16),
                                  e1 - __uint_as_float(p & 0xffff0000u));
            }
            *(uint4*)(sm3 + M3_AHI + off) = make_uint4(ph[0], ph[1], ph[2], ph[3]);
            *(uint4*)(sm3 + M3_ALO + off) = make_uint4(pl[0], pl[1], pl[2], pl[3]);
        }
    }
    __syncwarp();

    const int l7 = lane & 7;
    const uint32_t lxor = (uint32_t)l7 * 16u;
    const uint32_t aoff16 = (uint32_t)((lane >> 4) & 1) * 16u;
    const uint32_t boff16 = (uint32_t)((lane >> 3) & 1) * 16u;
    const uint32_t arow0 = (uint32_t)(wid * 32 + l7 + ((lane >> 3) & 1) * 8) * 128u;
    const uint32_t brow_l = (uint32_t)(((lane >> 4) & 1) * 8 + l7) * 128u;
    const int qr = lane >> 2, qc = lane & 3;
    const size_t rowG0 = (size_t)blockIdx.x * 256 + wid * 32 + qr;
    const uint32_t aHi = smem_base + M3_AHI, aLo = smem_base + M3_ALO;
    const uint32_t whi = smem_base + M3_WHI;
    unsigned long long* xgt = g_xg + (size_t)t * 128 * B_;

#pragma unroll
    for (int cd = 0; cd < 4; cd++) {
        float acc[2][4][2][4];
#pragma unroll
        for (int mt = 0; mt < 2; mt++)
#pragma unroll
            for (int g = 0; g < 4; g++)
#pragma unroll
                for (int ds = 0; ds < 2; ds++)
#pragma unroll
                    for (int z = 0; z < 4; z++) acc[mt][g][ds][z] = 0.f;
        const uint32_t brow_cd = (uint32_t)(cd * 16) * 128u + brow_l;
#pragma unroll
        for (int kt = 0; kt < 4; kt++) {
            const uint32_t acol = ((uint32_t)(kt * 32) + aoff16) ^ lxor;
            const uint32_t bcol = ((uint32_t)(kt * 32) + boff16) ^ lxor;
            uint32_t ah[2][4], al[2][4];
            ldsm4(ah[0], aHi + arow0 + acol);
            ldsm4(ah[1], aHi + arow0 + 2048u + acol);
            ldsm4(al[0], aLo + arow0 + acol);
            ldsm4(al[1], aLo + arow0 + 2048u + acol);
            uint32_t bh[4][4], bl[4][4];
#pragma unroll
            for (int g = 0; g < 4; g++) {
                ldsm4(bh[g], whi + (uint32_t)g * 8192u + brow_cd + bcol);
                ldsm4(bl[g], whi + 32768u + (uint32_t)g * 8192u + brow_cd + bcol);
            }
#pragma unroll
            for (int mt = 0; mt < 2; mt++)
#pragma unroll
                for (int g = 0; g < 4; g++)
#pragma unroll
                    for (int ds = 0; ds < 2; ds++) {
                        mma_bf16(acc[mt][g][ds], ah[mt], bh[g][ds*2], bh[g][ds*2+1]);
                        mma_bf16(acc[mt][g][ds], al[mt], bh[g][ds*2], bh[g][ds*2+1]);
                        mma_bf16(acc[mt][g][ds], ah[mt], bl[g][ds*2], bl[g][ds*2+1]);
                    }
        }
#pragma unroll
        for (int g = 0; g < 4; g++)
#pragma unroll
            for (int ds = 0; ds < 2; ds++) {
                const int pi = cd * 8 + ds * 4 + qc;
                float2 bs = *(const float2*)&sb[g * 64 + 2 * pi];
#pragma unroll
                for (int mt = 0; mt < 2; mt++)
#pragma unroll
                    for (int rr = 0; rr < 2; rr++) {
                        float v0 = acc[mt][g][ds][rr*2]     + bs.x;
                        float v1 = acc[mt][g][ds][rr*2 + 1] + bs.y;
                        unsigned long long pk;
                        PK64(v0, v1, pk);
                        xgt[(size_t)(g * 32 + pi) * B_ + rowG0 + mt * 16 + rr * 8] = pk;
                    }
            }
    }
}

// smem layout (bytes): A buffers 2x(hi 32K + lo 32K) @0..131072,
// W_hi @131072, W_lo @163840, bsum @196608
#define SW_OFF   131072u
#define SBIAS    196608u
#define LSTM_SMEM 197632

// ---------------- stage 4: HMMA 28-step LSTM, 512 thr (16 warps x 16 rows) ----------------
__global__ void __launch_bounds__(512, 1) k_lstm_mm(const float* __restrict__ bih,
                                                    const float* __restrict__ bhh,
                                                    float* __restrict__ out) {
    extern __shared__ __align__(16) uint8_t sm[];
    uint32_t smem_base;
    asm("{ .reg .u64 t; cvta.to.shared.u64 t, %1; cvt.u32.u64 %0, t; }"
        : "=r"(smem_base) : "l"(sm));
    float* sbsum = (float*)(sm + SBIAS);
    const int tid = threadIdx.x, wid = tid >> 5, lane = tid & 31;

    {   // Whh hi/lo tiles + biases
        const uint4* src = (const uint4*)g_wt;
        uint4* dst = (uint4*)(sm + SW_OFF);
        for (int i = tid; i < 65536 / 16; i += 512) dst[i] = src[i];
        if (tid < 256) sbsum[tid] = bih[tid] + bhh[tid];
    }
    __syncthreads();

    const int l7 = lane & 7;
    const uint32_t lxor = (uint32_t)l7 * 16u;
    const uint32_t aoff16 = (uint32_t)((lane >> 4) & 1) * 16u;
    const uint32_t boff16 = (uint32_t)((lane >> 3) & 1) * 16u;
    const uint32_t arow0 = (uint32_t)(wid * 16 + l7 + ((lane >> 3) & 1) * 8) * 128u;
    const uint32_t brow_l = (uint32_t)(((lane >> 4) & 1) * 8 + l7) * 128u;
    const int qr = lane >> 2, qc = lane & 3;
    const int rowL0 = wid * 16 + qr;
    const size_t rowG0 = (size_t)blockIdx.x * 256 + rowL0;

    float c[32];
#pragma unroll
    for (int i = 0; i < 32; i++) c[i] = 0.f;

#pragma unroll 1
    for (int s = 0; s < 28; s++) {
        if (s == 4) {  // swap weights: Whh -> Wih+Whh
            __syncthreads();
            const uint4* src = (const uint4*)(g_wt + 65536);
            uint4* dst = (uint4*)(sm + SW_OFF);
            for (int i = tid; i < 65536 / 16; i += 512) dst[i] = src[i];
            __syncthreads();
        }
        const uint32_t aRd = smem_base + (uint32_t)((s + 1) & 1) * 65536u;
        uint8_t* aWr = sm + (uint32_t)(s & 1) * 65536u;
        const uint32_t whi = smem_base + SW_OFF;
        const int tsel = (s < 3) ? s : 2;
        const unsigned long long* xbase = g_xg + (size_t)tsel * 128 * B_;

#pragma unroll
        for (int cd = 0; cd < 4; cd++) {
            float acc[4][2][4];
#pragma unroll
            for (int g = 0; g < 4; g++)
#pragma unroll
                for (int ds = 0; ds < 2; ds++)
#pragma unroll
                    for (int z = 0; z < 4; z++) acc[g][ds][z] = 0.f;

            if (s >= 1) {
                const uint32_t brow_cd = (uint32_t)(cd * 16) * 128u + brow_l;
#pragma unroll
                for (int kt = 0; kt < 4; kt++) {
                    const uint32_t acol = ((uint32_t)(kt * 32) + aoff16) ^ lxor;
                    const uint32_t bcol = ((uint32_t)(kt * 32) + boff16) ^ lxor;
                    uint32_t ah[4], al[4];
                    ldsm4(ah, aRd + arow0 + acol);
                    ldsm4(al, aRd + 32768u + arow0 + acol);
                    uint32_t bh[4][4], bl[4][4];
#pragma unroll
                    for (int g = 0; g < 4; g++) {
                        ldsm4(bh[g], whi + (uint32_t)g * 8192u + brow_cd + bcol);
                        ldsm4(bl[g], whi + 32768u + (uint32_t)g * 8192u + brow_cd + bcol);
                    }
#pragma unroll
                    for (int g = 0; g < 4; g++)
#pragma unroll
                        for (int ds = 0; ds < 2; ds++) {
                            mma_bf16(acc[g][ds], ah, bh[g][ds*2], bh[g][ds*2+1]);
                            mma_bf16(acc[g][ds], al, bh[g][ds*2], bh[g][ds*2+1]);
                            mma_bf16(acc[g][ds], ah, bl[g][ds*2], bl[g][ds*2+1]);
                        }
                }
            }

            // epilogue for this 16-d chunk
            const int pbase = cd * 8 + qc;
#pragma unroll
            for (int ds = 0; ds < 2; ds++) {
                const int dbase = cd * 16 + ds * 8 + 2 * qc;
                float2 bi, bf, bg, bo;
                if (s >= 4) {
                    bi = *(const float2*)&sbsum[0 * 64 + dbase];
                    bf = *(const float2*)&sbsum[1 * 64 + dbase];
                    bg = *(const float2*)&sbsum[2 * 64 + dbase];
                    bo = *(const float2*)&sbsum[3 * 64 + dbase];
                }
#pragma unroll
                for (int rr = 0; rr < 2; rr++) {
                    const int rowL = rowL0 + rr * 8;
                    float gi0 = acc[0][ds][rr*2], gi1 = acc[0][ds][rr*2+1];
                    float gf0 = acc[1][ds][rr*2], gf1 = acc[1][ds][rr*2+1];
                    float gg0 = acc[2][ds][rr*2], gg1 = acc[2][ds][rr*2+1];
                    float go0 = acc[3][ds][rr*2], go1 = acc[3][ds][rr*2+1];
                    if (s < 4) {
                        const unsigned long long* xp = xbase + (rowG0 + rr * 8);
                        const int pi = pbase + ds * 4;
                        float lo, hi;
                        unsigned long long v;
                        v = xp[(size_t)(0 * 32 + pi) * B_]; UNPK(v, lo, hi); gi0 += lo; gi1 += hi;
                        v = xp[(size_t)(1 * 32 + pi) * B_]; UNPK(v, lo, hi); gf0 += lo; gf1 += hi;
                        v = xp[(size_t)(2 * 32 + pi) * B_]; UNPK(v, lo, hi); gg0 += lo; gg1 += hi;
                        v = xp[(size_t)(3 * 32 + pi) * B_]; UNPK(v, lo, hi); go0 += lo; go1 += hi;
                    } else {
                        gi0 += bi.x; gi1 += bi.y;
                        gf0 += bf.x; gf1 += bf.y;
                        gg0 += bg.x; gg1 += bg.y;
                        go0 += bo.x; go1 += bo.y;
                    }
                    const int ci = ((cd * 2 + ds) * 2 + rr) * 2;
                    float h0, h1;
                    lstm_cell(gi0, gf0, gg0, go0, c[ci], h0);
                    lstm_cell(gi1, gf1, gg1, go1, c[ci + 1], h1);
                    // split h into bf16 hi/lo and store to next-step A tile
                    uint32_t ph = pack_bf16(h0, h1);
                    float e0 = h0 - __uint_as_float(ph << 16);
                    float e1 = h1 - __uint_as_float(ph & 0xffff0000u);
                    uint32_t pl = pack_bf16(e0, e1);
                    uint32_t soff = (uint32_t)rowL * 128u +
                                    (((uint32_t)(cd * 32 + ds * 16 + qc * 4)) ^ ((uint32_t)qr * 16u));
                    *(uint32_t*)(aWr + soff) = ph;
                    *(uint32_t*)(aWr + 32768u + soff) = pl;
                    if (s >= 3) {
                        float2 o2 = make_float2(h0, h1);
                        *(float2*)(out + ((rowG0 + rr * 8) * 25 + (s - 3)) * 64 + dbase) = o2;
                    }
                }
            }
        }
        __syncwarp();
    }
}

// ---------------- host ----------------
extern "C" void kernel_launch(void* const* d_in, const int* in_sizes, int n_in,
                              void* d_out, int out_size) {
    const float* x   = (const float*)d_in[0];
    const float* W1  = (const float*)d_in[1];
    const float* b1  = (const float*)d_in[2];
    const float* g1  = (const float*)d_in[3];
    const float* be1 = (const float*)d_in[4];
    const float* W2  = (const float*)d_in[5];
    const float* b2  = (const float*)d_in[6];
    const float* g2  = (const float*)d_in[7];
    const float* be2 = (const float*)d_in[8];
    const float* W3  = (const float*)d_in[9];
    const float* b3  = (const float*)d_in[10];
    const float* Wih = (const float*)d_in[11];
    const float* Whh = (const float*)d_in[12];
    const float* bih = (const float*)d_in[13];
    const float* bhh = (const float*)d_in[14];
    float* out = (float*)d_out;

    static bool attr_done = false;
    if (!attr_done) {
        cudaFuncSetAttribute(k_mlp3, cudaFuncAttributeMaxDynamicSharedMemorySize, M3_SMEM);
        cudaFuncSetAttribute(k_lstm_mm, cudaFuncAttributeMaxDynamicSharedMemorySize, LSTM_SMEM);
        attr_done = true;
    }

    dim3 gmlp(NBLK, T_);
    k_prep<<<64, 256>>>(Wih, Whh);
    k_mlp1<<<gmlp, 256>>>(x, W1, b1);
    k_stats<<<T_, 256>>>(0, g1, be1);
    k_mlp2<<<gmlp, 256>>>(W2, b2);
    k_stats<<<T_, 256>>>(1, g2, be2);
    k_mlp3<<<gmlp, 256, M3_SMEM>>>(W3, b3, bih, bhh);
    k_lstm_mm<<<NBLK, 512, LSTM_SMEM>>>(bih, bhh, out);
}

// round 7
// speedup vs baseline: 3.6508x; 1.0050x over previous
#include <cuda_runtime.h>
#include <cuda_bf16.h>
#include <cstdint>
#include <cstddef>

#define B_    32768
#define T_    3
#define D_    64
#define H_    32
#define NBLK  128   // B_/256

// ---------------- scratch (device globals: allocation-free) ----------------
__device__ float g_h1[(size_t)T_ * B_ * H_];
__device__ float g_h2[(size_t)T_ * B_ * H_];
__device__ unsigned long long g_xg[(size_t)T_ * 128 * B_]; // xg pairs [t][j/2][r]
__device__ float g_ps1[T_ * NBLK * H_];
__device__ float g_pq1[T_ * NBLK * H_];
__device__ float g_ps2[T_ * NBLK * H_];
__device__ float g_pq2[T_ * NBLK * H_];
__device__ float2 g_bn1[T_ * H_];   // (scale, shift)
__device__ float2 g_bn2[T_ * H_];
// weight tiles: 6 x [256 n][64 k] bf16, 128B rows, SW128-swizzled
// 0 = Whh_hi, 1 = Whh_lo, 2 = (Wih+Whh)_hi, 3 = (Wih+Whh)_lo, 4 = Wih_hi, 5 = Wih_lo
__device__ __align__(16) uint8_t g_wt[6 * 32768];

#define UNPK(v, lo, hi) do { unsigned _l, _h; \
    asm("mov.b64 {%0,%1}, %2;" : "=r"(_l), "=r"(_h) : "l"(v)); \
    lo = __uint_as_float(_l); hi = __uint_as_float(_h); } while (0)
#define PK64(lo, hi, v) asm("mov.b64 %0, {%1,%2};" : "=l"(v) : "r"(__float_as_uint(lo)), "r"(__float_as_uint(hi)))

__device__ __forceinline__ float ex2f(float x) {
    float r; asm("ex2.approx.ftz.f32 %0, %1;" : "=f"(r) : "f"(x)); return r;
}
__device__ __forceinline__ float rcpf(float x) {
    float r; asm("rcp.approx.ftz.f32 %0, %1;" : "=f"(r) : "f"(x)); return r;
}
// fused LSTM cell: cn = sig(f)c + sig(i)tanh(g); h = sig(o)tanh(cn). 7 MUFU total.
__device__ __forceinline__ void lstm_cell(float gi, float gf, float gg, float go,
                                          float& c, float& h) {
    const float L2E = 1.4426950408889634f;
    float a = ex2f(-L2E * gf);
    float u = ex2f(-L2E * gi);
    float b = ex2f(-2.f * L2E * gg);
    float pa = 1.f + a, pu = 1.f + u, pb = 1.f + b;
    float t1 = pu * pb;
    float cn = (c * t1 + (1.f - b) * pa) * rcpf(pa * t1);
    float v = ex2f(-L2E * go);
    float w = ex2f(-2.f * L2E * cn);
    c = cn;
    h = (1.f - w) * rcpf((1.f + v) * (1.f + w));
}
__host__ __device__ __forceinline__ uint32_t swz128(uint32_t o) {
    return o ^ ((o >> 3) & 0x70);
}

// ---------------- stage 1: h1 = x @ W1^T + b1, + batch partials ----------------
__global__ void __launch_bounds__(256) k_mlp1(const float* __restrict__ x,
                                              const float* __restrict__ W1,
                                              const float* __restrict__ b1) {
    __shared__ float sW[D_ * H_];
    __shared__ float sr0[8 * 32], sr1[8 * 32];
    int tid = threadIdx.x;
    int t = blockIdx.y;
    int r = blockIdx.x * 256 + tid;
    for (int i = tid; i < D_ * H_; i += 256) { int j = i >> 6, k = i & 63; sW[k * H_ + j] = W1[i]; }
    __syncthreads();

    float xr[64];
    const float4* xp = (const float4*)(x + ((size_t)t * B_ + r) * D_);
#pragma unroll
    for (int i = 0; i < 16; i++) {
        float4 v = xp[i];
        xr[4*i] = v.x; xr[4*i+1] = v.y; xr[4*i+2] = v.z; xr[4*i+3] = v.w;
    }
    float acc[32];
#pragma unroll
    for (int j = 0; j < 32; j++) acc[j] = __ldg(&b1[j]);
#pragma unroll
    for (int k = 0; k < 64; k++) {
        float xk = xr[k];
#pragma unroll
        for (int q = 0; q < 8; q++) {
            float4 w = *(const float4*)&sW[k * H_ + q * 4];
            acc[q*4+0] = fmaf(w.x, xk, acc[q*4+0]);
            acc[q*4+1] = fmaf(w.y, xk, acc[q*4+1]);
            acc[q*4+2] = fmaf(w.z, xk, acc[q*4+2]);
            acc[q*4+3] = fmaf(w.w, xk, acc[q*4+3]);
        }
    }
    float4* op = (float4*)(g_h1 + ((size_t)t * B_ + r) * H_);
#pragma unroll
    for (int q = 0; q < 8; q++) op[q] = make_float4(acc[q*4], acc[q*4+1], acc[q*4+2], acc[q*4+3]);

    int lane = tid & 31, wp = tid >> 5;
#pragma unroll
    for (int j = 0; j < 32; j++) {
        float s = acc[j], q = acc[j] * acc[j];
#pragma unroll
        for (int o = 16; o; o >>= 1) {
            s += __shfl_xor_sync(0xffffffffu, s, o);
            q += __shfl_xor_sync(0xffffffffu, q, o);
        }
        if (lane == 0) { sr0[wp * 32 + j] = s; sr1[wp * 32 + j] = q; }
    }
    __syncthreads();
    if (tid < 32) {
        float s = 0.f, q = 0.f;
#pragma unroll
        for (int w2 = 0; w2 < 8; w2++) { s += sr0[w2 * 32 + tid]; q += sr1[w2 * 32 + tid]; }
        g_ps1[(t * NBLK + blockIdx.x) * 32 + tid] = s;
        g_pq1[(t * NBLK + blockIdx.x) * 32 + tid] = q;
    }
}

// ---------------- BN stats reduce (parallel: 3 blocks x 256 thr) ----------------
__global__ void k_stats(int which, const float* __restrict__ gam, const float* __restrict__ bet) {
    __shared__ float ss[256], sq[256];
    int t = blockIdx.x;
    int tid = threadIdx.x;
    int ch = tid & 31, part = tid >> 5;
    const float* ps = which ? g_ps2 : g_ps1;
    const float* pq = which ? g_pq2 : g_pq1;
    float s = 0.f, q = 0.f;
#pragma unroll
    for (int b = 0; b < 16; b++) {
        int blk = part * 16 + b;
        s += ps[(t * NBLK + blk) * 32 + ch];
        q += pq[(t * NBLK + blk) * 32 + ch];
    }
    ss[tid] = s; sq[tid] = q;
    __syncthreads();
    if (tid < 32) {
#pragma unroll
        for (int p = 1; p < 8; p++) { s += ss[p * 32 + tid]; q += sq[p * 32 + tid]; }
        float m = s * (1.f / B_);
        float v = q * (1.f / B_) - m * m;
        float sc = gam[tid] * rsqrtf(v + 1e-5f);
        float2 o = make_float2(sc, bet[tid] - m * sc);
        if (which) g_bn2[t * 32 + tid] = o; else g_bn1[t * 32 + tid] = o;
    }
}

// ---------------- stage 2: h2 = relu(BN1(h1)) @ W2^T + b2, + partials ----------------
__global__ void __launch_bounds__(256) k_mlp2(const float* __restrict__ W2,
                                              const float* __restrict__ b2) {
    __shared__ float sW[H_ * H_];
    __shared__ float sr0[8 * 32], sr1[8 * 32];
    int tid = threadIdx.x;
    int t = blockIdx.y;
    int r = blockIdx.x * 256 + tid;
    for (int i = tid; i < H_ * H_; i += 256) { int j = i >> 5, k = i & 31; sW[k * H_ + j] = W2[i]; }
    __syncthreads();

    float a[32];
    const float4* hp = (const float4*)(g_h1 + ((size_t)t * B_ + r) * H_);
#pragma unroll
    for (int i = 0; i < 8; i++) {
        float4 v = hp[i];
        float2 s0 = g_bn1[t * 32 + i * 4 + 0]; a[i*4+0] = fmaxf(0.f, fmaf(v.x, s0.x, s0.y));
        float2 s1 = g_bn1[t * 32 + i * 4 + 1]; a[i*4+1] = fmaxf(0.f, fmaf(v.y, s1.x, s1.y));
        float2 s2 = g_bn1[t * 32 + i * 4 + 2]; a[i*4+2] = fmaxf(0.f, fmaf(v.z, s2.x, s2.y));
        float2 s3 = g_bn1[t * 32 + i * 4 + 3]; a[i*4+3] = fmaxf(0.f, fmaf(v.w, s3.x, s3.y));
    }
    float acc[32];
#pragma unroll
    for (int j = 0; j < 32; j++) acc[j] = __ldg(&b2[j]);
#pragma unroll
    for (int k = 0; k < 32; k++) {
        float ak = a[k];
#pragma unroll
        for (int q = 0; q < 8; q++) {
            float4 w = *(const float4*)&sW[k * H_ + q * 4];
            acc[q*4+0] = fmaf(w.x, ak, acc[q*4+0]);
            acc[q*4+1] = fmaf(w.y, ak, acc[q*4+1]);
            acc[q*4+2] = fmaf(w.z, ak, acc[q*4+2]);
            acc[q*4+3] = fmaf(w.w, ak, acc[q*4+3]);
        }
    }
    float4* op = (float4*)(g_h2 + ((size_t)t * B_ + r) * H_);
#pragma unroll
    for (int q = 0; q < 8; q++) op[q] = make_float4(acc[q*4], acc[q*4+1], acc[q*4+2], acc[q*4+3]);

    int lane = tid & 31, wp = tid >> 5;
#pragma unroll
    for (int j = 0; j < 32; j++) {
        float s = acc[j], q = acc[j] * acc[j];
#pragma unroll
        for (int o = 16; o; o >>= 1) {
            s += __shfl_xor_sync(0xffffffffu, s, o);
            q += __shfl_xor_sync(0xffffffffu, q, o);
        }
        if (lane == 0) { sr0[wp * 32 + j] = s; sr1[wp * 32 + j] = q; }
    }
    __syncthreads();
    if (tid < 32) {
        float s = 0.f, q = 0.f;
#pragma unroll
        for (int w2 = 0; w2 < 8; w2++) { s += sr0[w2 * 32 + tid]; q += sr1[w2 * 32 + tid]; }
        g_ps2[(t * NBLK + blockIdx.x) * 32 + tid] = s;
        g_pq2[(t * NBLK + blockIdx.x) * 32 + tid] = q;
    }
}

// ---------------- weight split/prep for HMMA tiles (parallel) ----------------
__global__ void k_prep(const float* __restrict__ Wih, const float* __restrict__ Whh) {
    int idx = blockIdx.x * 256 + threadIdx.x;   // 16384 total
    int n = idx >> 6, k = idx & 63;
    float whh = Whh[idx];
    float wih = Wih[idx];
    float ws = whh + wih;
    __nv_bfloat16 hh = __float2bfloat16_rn(whh);
    __nv_bfloat16 hl = __float2bfloat16_rn(whh - __bfloat162float(hh));
    __nv_bfloat16 sh = __float2bfloat16_rn(ws);
    __nv_bfloat16 sl = __float2bfloat16_rn(ws - __bfloat162float(sh));
    __nv_bfloat16 ih = __float2bfloat16_rn(wih);
    __nv_bfloat16 il = __float2bfloat16_rn(wih - __bfloat162float(ih));
    uint32_t off = swz128((uint32_t)(n * 128 + k * 2));
    *(__nv_bfloat16*)(g_wt + 0 * 32768 + off) = hh;
    *(__nv_bfloat16*)(g_wt + 1 * 32768 + off) = hl;
    *(__nv_bfloat16*)(g_wt + 2 * 32768 + off) = sh;
    *(__nv_bfloat16*)(g_wt + 3 * 32768 + off) = sl;
    *(__nv_bfloat16*)(g_wt + 4 * 32768 + off) = ih;
    *(__nv_bfloat16*)(g_wt + 5 * 32768 + off) = il;
}

// ---------------- HMMA helpers ----------------
__device__ __forceinline__ void mma_bf16(float d[4], const uint32_t a[4],
                                         uint32_t b0, uint32_t b1) {
    asm volatile(
        "mma.sync.aligned.m16n8k16.row.col.f32.bf16.bf16.f32 "
        "{%0,%1,%2,%3}, {%4,%5,%6,%7}, {%8,%9}, {%0,%1,%2,%3};"
        : "+f"(d[0]), "+f"(d[1]), "+f"(d[2]), "+f"(d[3])
        : "r"(a[0]), "r"(a[1]), "r"(a[2]), "r"(a[3]), "r"(b0), "r"(b1));
}
__device__ __forceinline__ void ldsm4(uint32_t r[4], uint32_t addr) {
    asm volatile("ldmatrix.sync.aligned.m8n8.x4.shared.b16 {%0,%1,%2,%3}, [%4];"
                 : "=r"(r[0]), "=r"(r[1]), "=r"(r[2]), "=r"(r[3]) : "r"(addr) : "memory");
}
__device__ __forceinline__ uint32_t pack_bf16(float lo, float hi) {
    uint32_t r;
    asm("cvt.rn.bf16x2.f32 %0, %1, %2;" : "=r"(r) : "f"(hi), "f"(lo));
    return r;
}

// ---- stage 3: enc = relu(BN2(h2)) @ W3^T + b3; xg = enc @ Wih^T + bsum (HMMA) ----
// grid 128, loop t inside (weights loaded once)
#define M3_AHI 0u
#define M3_ALO 32768u
#define M3_WHI 65536u
#define M3_SW3 131072u
#define M3_SB  139264u
#define M3_SMEM 140288
__global__ void __launch_bounds__(256) k_mlp3(const float* __restrict__ W3,
                                              const float* __restrict__ b3,
                                              const float* __restrict__ bih,
                                              const float* __restrict__ bhh) {
    extern __shared__ __align__(16) uint8_t sm3[];
    uint32_t smem_base;
    asm("{ .reg .u64 t; cvta.to.shared.u64 t, %1; cvt.u32.u64 %0, t; }"
        : "=r"(smem_base) : "l"(sm3));
    float* sW3 = (float*)(sm3 + M3_SW3);
    float* sb  = (float*)(sm3 + M3_SB);
    const int tid = threadIdx.x, wid = tid >> 5, lane = tid & 31;

    for (int i = tid; i < 2048; i += 256) { int j = i >> 5, k = i & 31; sW3[k * 64 + j] = W3[i]; }
    {
        const uint4* src = (const uint4*)(g_wt + 4 * 32768);
        uint4* dst = (uint4*)(sm3 + M3_WHI);
        for (int i = tid; i < 65536 / 16; i += 256) dst[i] = src[i];
    }
    sb[tid] = bih[tid] + bhh[tid];
    __syncthreads();

    const int l7 = lane & 7;
    const uint32_t lxor = (uint32_t)l7 * 16u;
    const uint32_t aoff16 = (uint32_t)((lane >> 4) & 1) * 16u;
    const uint32_t boff16 = (uint32_t)((lane >> 3) & 1) * 16u;
    const uint32_t arow0 = (uint32_t)(wid * 32 + l7 + ((lane >> 3) & 1) * 8) * 128u;
    const uint32_t brow_l = (uint32_t)(((lane >> 4) & 1) * 8 + l7) * 128u;
    const int qr = lane >> 2, qc = lane & 3;
    const size_t rowG0 = (size_t)blockIdx.x * 256 + wid * 32 + qr;
    const uint32_t aHi = smem_base + M3_AHI, aLo = smem_base + M3_ALO;
    const uint32_t whi = smem_base + M3_WHI;

#pragma unroll 1
    for (int t = 0; t < T_; t++) {
        // phase 1: enc for own row (= tid)
        const size_t r = (size_t)blockIdx.x * 256 + tid;
        float a[32];
        const float4* hp = (const float4*)(g_h2 + ((size_t)t * B_ + r) * H_);
#pragma unroll
        for (int i = 0; i < 8; i++) {
            float4 v = hp[i];
            float2 s0 = g_bn2[t * 32 + i * 4 + 0]; a[i*4+0] = fmaxf(0.f, fmaf(v.x, s0.x, s0.y));
            float2 s1 = g_bn2[t * 32 + i * 4 + 1]; a[i*4+1] = fmaxf(0.f, fmaf(v.y, s1.x, s1.y));
            float2 s2 = g_bn2[t * 32 + i * 4 + 2]; a[i*4+2] = fmaxf(0.f, fmaf(v.z, s2.x, s2.y));
            float2 s3 = g_bn2[t * 32 + i * 4 + 3]; a[i*4+3] = fmaxf(0.f, fmaf(v.w, s3.x, s3.y));
        }
        float e[64];
#pragma unroll
        for (int j = 0; j < 64; j++) e[j] = __ldg(&b3[j]);
#pragma unroll
        for (int k = 0; k < 32; k++) {
            float ak = a[k];
#pragma unroll
            for (int q = 0; q < 16; q++) {
                float4 w = *(const float4*)&sW3[k * 64 + q * 4];
                e[q*4+0] = fmaf(w.x, ak, e[q*4+0]);
                e[q*4+1] = fmaf(w.y, ak, e[q*4+1]);
                e[q*4+2] = fmaf(w.z, ak, e[q*4+2]);
                e[q*4+3] = fmaf(w.w, ak, e[q*4+3]);
            }
        }
        {
            const uint32_t rb = (uint32_t)tid * 128u;
            const uint32_t rx = (uint32_t)(tid & 7) * 16u;
#pragma unroll
            for (int q = 0; q < 8; q++) {
                uint32_t off = rb + (((uint32_t)q * 16u) ^ rx);
                uint32_t ph[4], pl[4];
#pragma unroll
                for (int j = 0; j < 4; j++) {
                    float e0 = e[q*8 + 2*j], e1 = e[q*8 + 2*j + 1];
                    uint32_t p = pack_bf16(e0, e1);
                    ph[j] = p;
                    pl[j] = pack_bf16(e0 - __uint_as_float(p << 16),
                                      e1 - __uint_as_float(p & 0xffff0000u));
                }
                *(uint4*)(sm3 + M3_AHI + off) = make_uint4(ph[0], ph[1], ph[2], ph[3]);
                *(uint4*)(sm3 + M3_ALO + off) = make_uint4(pl[0], pl[1], pl[2], pl[3]);
            }
        }
        __syncwarp();

        // phase 2: xg = enc @ Wih^T + bsum via HMMA (warp-private rows)
        unsigned long long* xgt = g_xg + (size_t)t * 128 * B_;
#pragma unroll
        for (int cd = 0; cd < 4; cd++) {
            float acc[2][4][2][4];
#pragma unroll
            for (int mt = 0; mt < 2; mt++)
#pragma unroll
                for (int g = 0; g < 4; g++)
#pragma unroll
                    for (int ds = 0; ds < 2; ds++)
#pragma unroll
                        for (int z = 0; z < 4; z++) acc[mt][g][ds][z] = 0.f;
            const uint32_t brow_cd = (uint32_t)(cd * 16) * 128u + brow_l;
#pragma unroll
            for (int kt = 0; kt < 4; kt++) {
                const uint32_t acol = ((uint32_t)(kt * 32) + aoff16) ^ lxor;
                const uint32_t bcol = ((uint32_t)(kt * 32) + boff16) ^ lxor;
                uint32_t ah[2][4], al[2][4];
                ldsm4(ah[0], aHi + arow0 + acol);
                ldsm4(ah[1], aHi + arow0 + 2048u + acol);
                ldsm4(al[0], aLo + arow0 + acol);
                ldsm4(al[1], aLo + arow0 + 2048u + acol);
                uint32_t bh[4][4], bl[4][4];
#pragma unroll
                for (int g = 0; g < 4; g++) {
                    ldsm4(bh[g], whi + (uint32_t)g * 8192u + brow_cd + bcol);
                    ldsm4(bl[g], whi + 32768u + (uint32_t)g * 8192u + brow_cd + bcol);
                }
#pragma unroll
                for (int mt = 0; mt < 2; mt++)
#pragma unroll
                    for (int g = 0; g < 4; g++)
#pragma unroll
                        for (int ds = 0; ds < 2; ds++) {
                            mma_bf16(acc[mt][g][ds], ah[mt], bh[g][ds*2], bh[g][ds*2+1]);
                            mma_bf16(acc[mt][g][ds], al[mt], bh[g][ds*2], bh[g][ds*2+1]);
                            mma_bf16(acc[mt][g][ds], ah[mt], bl[g][ds*2], bl[g][ds*2+1]);
                        }
            }
#pragma unroll
            for (int g = 0; g < 4; g++)
#pragma unroll
                for (int ds = 0; ds < 2; ds++) {
                    const int pi = cd * 8 + ds * 4 + qc;
                    float2 bs = *(const float2*)&sb[g * 64 + 2 * pi];
#pragma unroll
                    for (int mt = 0; mt < 2; mt++)
#pragma unroll
                        for (int rr = 0; rr < 2; rr++) {
                            float v0 = acc[mt][g][ds][rr*2]     + bs.x;
                            float v1 = acc[mt][g][ds][rr*2 + 1] + bs.y;
                            unsigned long long pk;
                            PK64(v0, v1, pk);
                            xgt[(size_t)(g * 32 + pi) * B_ + rowG0 + mt * 16 + rr * 8] = pk;
                        }
                }
        }
        __syncwarp();
    }
}

// ---------------- stage 4: HMMA 28-step LSTM, grid 148 x 448 thr ----------------
// 14 warps/CTA, each warp owns 16-row group G = blockIdx.x + 148*wid (G < 2048)
// smem (bytes): A dbl buffers: buf = (s&1)*57344, hi @buf, lo @buf+28672 (224 rows x 128B)
//               W hi @114688, lo @147456, bias @180224
#define LA_BUF   57344u
#define LA_LO    28672u
#define LW_OFF   114688u
#define LBIAS    180224u
#define LSTM_SMEM 181248

__global__ void __launch_bounds__(448, 1) k_lstm_mm(const float* __restrict__ bih,
                                                    const float* __restrict__ bhh,
                                                    float* __restrict__ out) {
    extern __shared__ __align__(16) uint8_t sm[];
    uint32_t smem_base;
    asm("{ .reg .u64 t; cvta.to.shared.u64 t, %1; cvt.u32.u64 %0, t; }"
        : "=r"(smem_base) : "l"(sm));
    float* sbsum = (float*)(sm + LBIAS);
    const int tid = threadIdx.x, wid = tid >> 5, lane = tid & 31;

    {   // Whh hi/lo tiles + biases
        const uint4* src = (const uint4*)g_wt;
        uint4* dst = (uint4*)(sm + LW_OFF);
        for (int i = tid; i < 65536 / 16; i += 448) dst[i] = src[i];
        if (tid < 256) sbsum[tid] = bih[tid] + bhh[tid];
    }
    __syncthreads();

    const int G = blockIdx.x + 148 * wid;          // 16-row group id
    const bool act = (G < 2048);
    const int l7 = lane & 7;
    const uint32_t lxor = (uint32_t)l7 * 16u;
    const uint32_t aoff16 = (uint32_t)((lane >> 4) & 1) * 16u;
    const uint32_t boff16 = (uint32_t)((lane >> 3) & 1) * 16u;
    const uint32_t arow0 = (uint32_t)(wid * 16 + l7 + ((lane >> 3) & 1) * 8) * 128u;
    const uint32_t brow_l = (uint32_t)(((lane >> 4) & 1) * 8 + l7) * 128u;
    const int qr = lane >> 2, qc = lane & 3;
    const int rowL0 = wid * 16 + qr;               // local A-tile row
    const size_t rowG0 = (size_t)G * 16 + qr;      // global row

    float c[32];
#pragma unroll
    for (int i = 0; i < 32; i++) c[i] = 0.f;

#pragma unroll 1
    for (int s = 0; s < 28; s++) {
        if (s == 4) {  // swap weights: Whh -> Wih+Whh
            __syncthreads();
            const uint4* src = (const uint4*)(g_wt + 65536);
            uint4* dst = (uint4*)(sm + LW_OFF);
            for (int i = tid; i < 65536 / 16; i += 448) dst[i] = src[i];
            __syncthreads();
        }
        const uint32_t aRd = smem_base + (uint32_t)((s + 1) & 1) * LA_BUF;
        uint8_t* aWr = sm + (uint32_t)(s & 1) * LA_BUF;
        const uint32_t whi = smem_base + LW_OFF;
        const int tsel = (s < 3) ? s : 2;
        const unsigned long long* xbase = g_xg + (size_t)tsel * 128 * B_;

#pragma unroll
        for (int cd = 0; cd < 4; cd++) {
            float acc[4][2][4];
#pragma unroll
            for (int g = 0; g < 4; g++)
#pragma unroll
                for (int ds = 0; ds < 2; ds++)
#pragma unroll
                    for (int z = 0; z < 4; z++) acc[g][ds][z] = 0.f;

            if (s >= 1) {
                const uint32_t brow_cd = (uint32_t)(cd * 16) * 128u + brow_l;
#pragma unroll
                for (int kt = 0; kt < 4; kt++) {
                    const uint32_t acol = ((uint32_t)(kt * 32) + aoff16) ^ lxor;
                    const uint32_t bcol = ((uint32_t)(kt * 32) + boff16) ^ lxor;
                    uint32_t ah[4], al[4];
                    ldsm4(ah, aRd + arow0 + acol);
                    ldsm4(al, aRd + LA_LO + arow0 + acol);
                    uint32_t bh[4][4], bl[4][4];
#pragma unroll
                    for (int g = 0; g < 4; g++) {
                        ldsm4(bh[g], whi + (uint32_t)g * 8192u + brow_cd + bcol);
                        ldsm4(bl[g], whi + 32768u + (uint32_t)g * 8192u + brow_cd + bcol);
                    }
#pragma unroll
                    for (int g = 0; g < 4; g++)
#pragma unroll
                        for (int ds = 0; ds < 2; ds++) {
                            mma_bf16(acc[g][ds], ah, bh[g][ds*2], bh[g][ds*2+1]);
                            mma_bf16(acc[g][ds], al, bh[g][ds*2], bh[g][ds*2+1]);
                            mma_bf16(acc[g][ds], ah, bl[g][ds*2], bl[g][ds*2+1]);
                        }
                }
            }

            // epilogue for this 16-d chunk
            const int pbase = cd * 8 + qc;
#pragma unroll
            for (int ds = 0; ds < 2; ds++) {
                const int dbase = cd * 16 + ds * 8 + 2 * qc;
                float2 bi, bf, bg, bo;
                if (s >= 4) {
                    bi = *(const float2*)&sbsum[0 * 64 + dbase];
                    bf = *(const float2*)&sbsum[1 * 64 + dbase];
                    bg = *(const float2*)&sbsum[2 * 64 + dbase];
                    bo = *(const float2*)&sbsum[3 * 64 + dbase];
                }
#pragma unroll
                for (int rr = 0; rr < 2; rr++) {
                    const int rowL = rowL0 + rr * 8;
                    float gi0 = acc[0][ds][rr*2], gi1 = acc[0][ds][rr*2+1];
                    float gf0 = acc[1][ds][rr*2], gf1 = acc[1][ds][rr*2+1];
                    float gg0 = acc[2][ds][rr*2], gg1 = acc[2][ds][rr*2+1];
                    float go0 = acc[3][ds][rr*2], go1 = acc[3][ds][rr*2+1];
                    if (s < 4) {
                        const int pi = pbase + ds * 4;
                        float lo, hi;
                        unsigned long long v;
                        if (act) {
                            const unsigned long long* xp = xbase + (rowG0 + rr * 8);
                            v = xp[(size_t)(0 * 32 + pi) * B_]; UNPK(v, lo, hi); gi0 += lo; gi1 += hi;
                            v = xp[(size_t)(1 * 32 + pi) * B_]; UNPK(v, lo, hi); gf0 += lo; gf1 += hi;
                            v = xp[(size_t)(2 * 32 + pi) * B_]; UNPK(v, lo, hi); gg0 += lo; gg1 += hi;
                            v = xp[(size_t)(3 * 32 + pi) * B_]; UNPK(v, lo, hi); go0 += lo; go1 += hi;
                        }
                    } else {
                        gi0 += bi.x; gi1 += bi.y;
                        gf0 += bf.x; gf1 += bf.y;
                        gg0 += bg.x; gg1 += bg.y;
                        go0 += bo.x; go1 += bo.y;
                    }
                    const int ci = ((cd * 2 + ds) * 2 + rr) * 2;
                    float h0, h1;
                    lstm_cell(gi0, gf0, gg0, go0, c[ci], h0);
                    lstm_cell(gi1, gf1, gg1, go1, c[ci + 1], h1);
                    // split h into bf16 hi/lo and store to next-step A tile
                    uint32_t ph = pack_bf16(h0, h1);
                    float e0 = h0 - __uint_as_float(ph << 16);
                    float e1 = h1 - __uint_as_float(ph & 0xffff0000u);
                    uint32_t pl = pack_bf16(e0, e1);
                    uint32_t soff = (uint32_t)rowL * 128u +
                                    (((uint32_t)(cd * 32 + ds * 16 + qc * 4)) ^ ((uint32_t)qr * 16u));
                    *(uint32_t*)(aWr + soff) = ph;
                    *(uint32_t*)(aWr + LA_LO + soff) = pl;
                    if (s >= 3 && act) {
                        float2 o2 = make_float2(h0, h1);
                        *(float2*)(out + ((rowG0 + rr * 8) * 25 + (s - 3)) * 64 + dbase) = o2;
                    }
                }
            }
        }
        __syncwarp();
    }
}

// ---------------- host ----------------
extern "C" void kernel_launch(void* const* d_in, const int* in_sizes, int n_in,
                              void* d_out, int out_size) {
    const float* x   = (const float*)d_in[0];
    const float* W1  = (const float*)d_in[1];
    const float* b1  = (const float*)d_in[2];
    const float* g1  = (const float*)d_in[3];
    const float* be1 = (const float*)d_in[4];
    const float* W2  = (const float*)d_in[5];
    const float* b2  = (const float*)d_in[6];
    const float* g2  = (const float*)d_in[7];
    const float* be2 = (const float*)d_in[8];
    const float* W3  = (const float*)d_in[9];
    const float* b3  = (const float*)d_in[10];
    const float* Wih = (const float*)d_in[11];
    const float* Whh = (const float*)d_in[12];
    const float* bih = (const float*)d_in[13];
    const float* bhh = (const float*)d_in[14];
    float* out = (float*)d_out;

    static bool attr_done = false;
    if (!attr_done) {
        cudaFuncSetAttribute(k_mlp3, cudaFuncAttributeMaxDynamicSharedMemorySize, M3_SMEM);
        cudaFuncSetAttribute(k_lstm_mm, cudaFuncAttributeMaxDynamicSharedMemorySize, LSTM_SMEM);
        attr_done = true;
    }

    dim3 gmlp(NBLK, T_);
    k_prep<<<64, 256>>>(Wih, Whh);
    k_mlp1<<<gmlp, 256>>>(x, W1, b1);
    k_stats<<<T_, 256>>>(0, g1, be1);
    k_mlp2<<<gmlp, 256>>>(W2, b2);
    k_stats<<<T_, 256>>>(1, g2, be2);
    k_mlp3<<<NBLK, 256, M3_SMEM>>>(W3, b3, bih, bhh);
    k_lstm_mm<<<148, 448, LSTM_SMEM>>>(bih, bhh, out);
}

// round 8
// speedup vs baseline: 3.6624x; 1.0032x over previous
#include <cuda_runtime.h>
#include <cuda_bf16.h>
#include <cstdint>
#include <cstddef>

#define B_    32768
#define T_    3
#define D_    64
#define H_    32
#define NBLK  128   // B_/256

// ---------------- scratch (device globals: allocation-free) ----------------
__device__ float g_h1[(size_t)T_ * B_ * H_];
__device__ float g_h2[(size_t)T_ * B_ * H_];
__device__ unsigned long long g_xg[(size_t)T_ * 128 * B_]; // xg pairs [t][j/2][r]
__device__ float g_ps1[T_ * NBLK * H_];
__device__ float g_pq1[T_ * NBLK * H_];
__device__ float g_ps2[T_ * NBLK * H_];
__device__ float g_pq2[T_ * NBLK * H_];
__device__ float2 g_bn1[T_ * H_];   // (scale, shift)
__device__ float2 g_bn2[T_ * H_];
__device__ int g_c1[T_];            // last-block counters (self-resetting)
__device__ int g_c2[T_];
// weight tiles: 6 x [256 n][64 k] bf16, 128B rows, SW128-swizzled
// 0 = Whh_hi, 1 = Whh_lo, 2 = (Wih+Whh)_hi, 3 = (Wih+Whh)_lo, 4 = Wih_hi, 5 = Wih_lo
__device__ __align__(16) uint8_t g_wt[6 * 32768];

#define UNPK(v, lo, hi) do { unsigned _l, _h; \
    asm("mov.b64 {%0,%1}, %2;" : "=r"(_l), "=r"(_h) : "l"(v)); \
    lo = __uint_as_float(_l); hi = __uint_as_float(_h); } while (0)
#define PK64(lo, hi, v) asm("mov.b64 %0, {%1,%2};" : "=l"(v) : "r"(__float_as_uint(lo)), "r"(__float_as_uint(hi)))

__device__ __forceinline__ float ex2f(float x) {
    float r; asm("ex2.approx.ftz.f32 %0, %1;" : "=f"(r) : "f"(x)); return r;
}
__device__ __forceinline__ float rcpf(float x) {
    float r; asm("rcp.approx.ftz.f32 %0, %1;" : "=f"(r) : "f"(x)); return r;
}
// paired LSTM cells: shares RCPs between the two cells. 12 MUFU / pair.
__device__ __forceinline__ void lstm_cell2(float gi0, float gf0, float gg0, float go0,
                                           float gi1, float gf1, float gg1, float go1,
                                           float& c0, float& c1, float& h0, float& h1) {
    const float L2E = 1.4426950408889634f;
    float a0 = ex2f(-L2E * gf0), u0 = ex2f(-L2E * gi0), b0 = ex2f(-2.f * L2E * gg0);
    float a1 = ex2f(-L2E * gf1), u1 = ex2f(-L2E * gi1), b1 = ex2f(-2.f * L2E * gg1);
    float pa0 = 1.f + a0, t0 = (1.f + u0) * (1.f + b0);
    float pa1 = 1.f + a1, t1 = (1.f + u1) * (1.f + b1);
    float D0 = pa0 * t0, N0 = c0 * t0 + (1.f - b0) * pa0;
    float D1 = pa1 * t1, N1 = c1 * t1 + (1.f - b1) * pa1;
    float r = rcpf(D0 * D1);
    float cn0 = N0 * (r * D1), cn1 = N1 * (r * D0);
    float v0 = ex2f(-L2E * go0), w0 = ex2f(-2.f * L2E * cn0);
    float v1 = ex2f(-L2E * go1), w1 = ex2f(-2.f * L2E * cn1);
    float P0 = (1.f + v0) * (1.f + w0), P1 = (1.f + v1) * (1.f + w1);
    float r2 = rcpf(P0 * P1);
    c0 = cn0; c1 = cn1;
    h0 = (1.f - w0) * (r2 * P1);
    h1 = (1.f - w1) * (r2 * P0);
}
__host__ __device__ __forceinline__ uint32_t swz128(uint32_t o) {
    return o ^ ((o >> 3) & 0x70);
}
__device__ __forceinline__ uint32_t pack_bf16(float lo, float hi) {
    uint32_t r;
    asm("cvt.rn.bf16x2.f32 %0, %1, %2;" : "=r"(r) : "f"(hi), "f"(lo));
    return r;
}

// ---------------- stage 1: h1 = x @ W1^T + b1, + fused BN1 stats + weight prep ----------------
__global__ void __launch_bounds__(256) k_mlp1(const float* __restrict__ x,
                                              const float* __restrict__ W1,
                                              const float* __restrict__ b1,
                                              const float* __restrict__ g1,
                                              const float* __restrict__ be1,
                                              const float* __restrict__ Wih,
                                              const float* __restrict__ Whh) {
    __shared__ float sW[D_ * H_];
    __shared__ float sacc[256 * 33];
    __shared__ float sr0[8 * 32], sr1[8 * 32];
    __shared__ int sflag;
    int tid = threadIdx.x;
    int t = blockIdx.y;
    int r = blockIdx.x * 256 + tid;
    for (int i = tid; i < D_ * H_; i += 256) { int j = i >> 6, k = i & 63; sW[k * H_ + j] = W1[i]; }
    __syncthreads();

    float xr[64];
    const float4* xp = (const float4*)(x + ((size_t)t * B_ + r) * D_);
#pragma unroll
    for (int i = 0; i < 16; i++) {
        float4 v = xp[i];
        xr[4*i] = v.x; xr[4*i+1] = v.y; xr[4*i+2] = v.z; xr[4*i+3] = v.w;
    }
    float acc[32];
#pragma unroll
    for (int j = 0; j < 32; j++) acc[j] = __ldg(&b1[j]);
#pragma unroll
    for (int k = 0; k < 64; k++) {
        float xk = xr[k];
#pragma unroll
        for (int q = 0; q < 8; q++) {
            float4 w = *(const float4*)&sW[k * H_ + q * 4];
            acc[q*4+0] = fmaf(w.x, xk, acc[q*4+0]);
            acc[q*4+1] = fmaf(w.y, xk, acc[q*4+1]);
            acc[q*4+2] = fmaf(w.z, xk, acc[q*4+2]);
            acc[q*4+3] = fmaf(w.w, xk, acc[q*4+3]);
        }
    }
    float4* op = (float4*)(g_h1 + ((size_t)t * B_ + r) * H_);
#pragma unroll
    for (int q = 0; q < 8; q++) op[q] = make_float4(acc[q*4], acc[q*4+1], acc[q*4+2], acc[q*4+3]);

    // smem transpose reduction for batch stats
#pragma unroll
    for (int j = 0; j < 32; j++) sacc[tid * 33 + j] = acc[j];
    __syncthreads();
    int part = tid >> 5, ch = tid & 31;
    {
        float s = 0.f, q = 0.f;
#pragma unroll
        for (int rr = 0; rr < 32; rr++) {
            float v = sacc[(part * 32 + rr) * 33 + ch];
            s += v; q = fmaf(v, v, q);
        }
        sr0[part * 32 + ch] = s;
        sr1[part * 32 + ch] = q;
    }
    __syncthreads();
    if (tid < 32) {
        float s = 0.f, q = 0.f;
#pragma unroll
        for (int p = 0; p < 8; p++) { s += sr0[p * 32 + tid]; q += sr1[p * 32 + tid]; }
        g_ps1[(t * NBLK + blockIdx.x) * 32 + tid] = s;
        g_pq1[(t * NBLK + blockIdx.x) * 32 + tid] = q;
    }

    // fused weight prep (bf16 hi/lo splits), frame-0 blocks 0..63 only
    if (t == 0 && blockIdx.x < 64) {
        int idx = blockIdx.x * 256 + tid;   // < 16384
        int n = idx >> 6, k = idx & 63;
        float whh = Whh[idx];
        float wih = Wih[idx];
        float ws = whh + wih;
        __nv_bfloat16 hh = __float2bfloat16_rn(whh);
        __nv_bfloat16 hl = __float2bfloat16_rn(whh - __bfloat162float(hh));
        __nv_bfloat16 sh = __float2bfloat16_rn(ws);
        __nv_bfloat16 sl = __float2bfloat16_rn(ws - __bfloat162float(sh));
        __nv_bfloat16 ih = __float2bfloat16_rn(wih);
        __nv_bfloat16 il = __float2bfloat16_rn(wih - __bfloat162float(ih));
        uint32_t off = swz128((uint32_t)(n * 128 + k * 2));
        *(__nv_bfloat16*)(g_wt + 0 * 32768 + off) = hh;
        *(__nv_bfloat16*)(g_wt + 1 * 32768 + off) = hl;
        *(__nv_bfloat16*)(g_wt + 2 * 32768 + off) = sh;
        *(__nv_bfloat16*)(g_wt + 3 * 32768 + off) = sl;
        *(__nv_bfloat16*)(g_wt + 4 * 32768 + off) = ih;
        *(__nv_bfloat16*)(g_wt + 5 * 32768 + off) = il;
    }

    // last block per frame computes BN scale/shift
    __syncthreads();
    __threadfence();
    if (tid == 0) sflag = (atomicAdd(&g_c1[t], 1) == NBLK - 1);
    __syncthreads();
    if (sflag) {
        __threadfence();
        float s = 0.f, q = 0.f;
        for (int b = part; b < NBLK; b += 8) {
            s += g_ps1[(t * NBLK + b) * 32 + ch];
            q += g_pq1[(t * NBLK + b) * 32 + ch];
        }
        sr0[part * 32 + ch] = s;
        sr1[part * 32 + ch] = q;
        __syncthreads();
        if (tid < 32) {
            float s3 = 0.f, q3 = 0.f;
#pragma unroll
            for (int p = 0; p < 8; p++) { s3 += sr0[p * 32 + tid]; q3 += sr1[p * 32 + tid]; }
            float m = s3 * (1.f / B_);
            float v = q3 * (1.f / B_) - m * m;
            float sc = g1[tid] * rsqrtf(v + 1e-5f);
            g_bn1[t * 32 + tid] = make_float2(sc, be1[tid] - m * sc);
        }
        if (tid == 0) g_c1[t] = 0;   // reset for next graph replay
    }
}

// ---------------- stage 2: h2 = relu(BN1(h1)) @ W2^T + b2, + fused BN2 stats ----------------
__global__ void __launch_bounds__(256) k_mlp2(const float* __restrict__ W2,
                                              const float* __restrict__ b2,
                                              const float* __restrict__ g2,
                                              const float* __restrict__ be2) {
    __shared__ float sW[H_ * H_];
    __shared__ float sacc[256 * 33];
    __shared__ float sr0[8 * 32], sr1[8 * 32];
    __shared__ int sflag;
    int tid = threadIdx.x;
    int t = blockIdx.y;
    int r = blockIdx.x * 256 + tid;
    for (int i = tid; i < H_ * H_; i += 256) { int j = i >> 5, k = i & 31; sW[k * H_ + j] = W2[i]; }
    __syncthreads();

    float a[32];
    const float4* hp = (const float4*)(g_h1 + ((size_t)t * B_ + r) * H_);
#pragma unroll
    for (int i = 0; i < 8; i++) {
        float4 v = hp[i];
        float2 s0 = g_bn1[t * 32 + i * 4 + 0]; a[i*4+0] = fmaxf(0.f, fmaf(v.x, s0.x, s0.y));
        float2 s1 = g_bn1[t * 32 + i * 4 + 1]; a[i*4+1] = fmaxf(0.f, fmaf(v.y, s1.x, s1.y));
        float2 s2 = g_bn1[t * 32 + i * 4 + 2]; a[i*4+2] = fmaxf(0.f, fmaf(v.z, s2.x, s2.y));
        float2 s3 = g_bn1[t * 32 + i * 4 + 3]; a[i*4+3] = fmaxf(0.f, fmaf(v.w, s3.x, s3.y));
    }
    float acc[32];
#pragma unroll
    for (int j = 0; j < 32; j++) acc[j] = __ldg(&b2[j]);
#pragma unroll
    for (int k = 0; k < 32; k++) {
        float ak = a[k];
#pragma unroll
        for (int q = 0; q < 8; q++) {
            float4 w = *(const float4*)&sW[k * H_ + q * 4];
            acc[q*4+0] = fmaf(w.x, ak, acc[q*4+0]);
            acc[q*4+1] = fmaf(w.y, ak, acc[q*4+1]);
            acc[q*4+2] = fmaf(w.z, ak, acc[q*4+2]);
            acc[q*4+3] = fmaf(w.w, ak, acc[q*4+3]);
        }
    }
    float4* op = (float4*)(g_h2 + ((size_t)t * B_ + r) * H_);
#pragma unroll
    for (int q = 0; q < 8; q++) op[q] = make_float4(acc[q*4], acc[q*4+1], acc[q*4+2], acc[q*4+3]);

#pragma unroll
    for (int j = 0; j < 32; j++) sacc[tid * 33 + j] = acc[j];
    __syncthreads();
    int part = tid >> 5, ch = tid & 31;
    {
        float s = 0.f, q = 0.f;
#pragma unroll
        for (int rr = 0; rr < 32; rr++) {
            float v = sacc[(part * 32 + rr) * 33 + ch];
            s += v; q = fmaf(v, v, q);
        }
        sr0[part * 32 + ch] = s;
        sr1[part * 32 + ch] = q;
    }
    __syncthreads();
    if (tid < 32) {
        float s = 0.f, q = 0.f;
#pragma unroll
        for (int p = 0; p < 8; p++) { s += sr0[p * 32 + tid]; q += sr1[p * 32 + tid]; }
        g_ps2[(t * NBLK + blockIdx.x) * 32 + tid] = s;
        g_pq2[(t * NBLK + blockIdx.x) * 32 + tid] = q;
    }
    __syncthreads();
    __threadfence();
    if (tid == 0) sflag = (atomicAdd(&g_c2[t], 1) == NBLK - 1);
    __syncthreads();
    if (sflag) {
        __threadfence();
        float s = 0.f, q = 0.f;
        for (int b = part; b < NBLK; b += 8) {
            s += g_ps2[(t * NBLK + b) * 32 + ch];
            q += g_pq2[(t * NBLK + b) * 32 + ch];
        }
        sr0[part * 32 + ch] = s;
        sr1[part * 32 + ch] = q;
        __syncthreads();
        if (tid < 32) {
            float s3 = 0.f, q3 = 0.f;
#pragma unroll
            for (int p = 0; p < 8; p++) { s3 += sr0[p * 32 + tid]; q3 += sr1[p * 32 + tid]; }
            float m = s3 * (1.f / B_);
            float v = q3 * (1.f / B_) - m * m;
            float sc = g2[tid] * rsqrtf(v + 1e-5f);
            g_bn2[t * 32 + tid] = make_float2(sc, be2[tid] - m * sc);
        }
        if (tid == 0) g_c2[t] = 0;
    }
}

// ---------------- HMMA helpers ----------------
__device__ __forceinline__ void mma_bf16(float d[4], const uint32_t a[4],
                                         uint32_t b0, uint32_t b1) {
    asm volatile(
        "mma.sync.aligned.m16n8k16.row.col.f32.bf16.bf16.f32 "
        "{%0,%1,%2,%3}, {%4,%5,%6,%7}, {%8,%9}, {%0,%1,%2,%3};"
        : "+f"(d[0]), "+f"(d[1]), "+f"(d[2]), "+f"(d[3])
        : "r"(a[0]), "r"(a[1]), "r"(a[2]), "r"(a[3]), "r"(b0), "r"(b1));
}
__device__ __forceinline__ void ldsm4(uint32_t r[4], uint32_t addr) {
    asm volatile("ldmatrix.sync.aligned.m8n8.x4.shared.b16 {%0,%1,%2,%3}, [%4];"
                 : "=r"(r[0]), "=r"(r[1]), "=r"(r[2]), "=r"(r[3]) : "r"(addr) : "memory");
}

// ---- stage 3: enc = relu(BN2(h2)) @ W3^T + b3; xg = enc @ Wih^T + bsum (HMMA) ----
// grid 128, loop t inside (weights loaded once)
#define M3_AHI 0u
#define M3_ALO 32768u
#define M3_WHI 65536u
#define M3_SW3 131072u
#define M3_SB  139264u
#define M3_SMEM 140288
__global__ void __launch_bounds__(256) k_mlp3(const float* __restrict__ W3,
                                              const float* __restrict__ b3,
                                              const float* __restrict__ bih,
                                              const float* __restrict__ bhh) {
    extern __shared__ __align__(16) uint8_t sm3[];
    uint32_t smem_base;
    asm("{ .reg .u64 t; cvta.to.shared.u64 t, %1; cvt.u32.u64 %0, t; }"
        : "=r"(smem_base) : "l"(sm3));
    float* sW3 = (float*)(sm3 + M3_SW3);
    float* sb  = (float*)(sm3 + M3_SB);
    const int tid = threadIdx.x, wid = tid >> 5, lane = tid & 31;

    for (int i = tid; i < 2048; i += 256) { int j = i >> 5, k = i & 31; sW3[k * 64 + j] = W3[i]; }
    {
        const uint4* src = (const uint4*)(g_wt + 4 * 32768);
        uint4* dst = (uint4*)(sm3 + M3_WHI);
        for (int i = tid; i < 65536 / 16; i += 256) dst[i] = src[i];
    }
    sb[tid] = bih[tid] + bhh[tid];
    __syncthreads();

    const int l7 = lane & 7;
    const uint32_t lxor = (uint32_t)l7 * 16u;
    const uint32_t aoff16 = (uint32_t)((lane >> 4) & 1) * 16u;
    const uint32_t boff16 = (uint32_t)((lane >> 3) & 1) * 16u;
    const uint32_t arow0 = (uint32_t)(wid * 32 + l7 + ((lane >> 3) & 1) * 8) * 128u;
    const uint32_t brow_l = (uint32_t)(((lane >> 4) & 1) * 8 + l7) * 128u;
    const int qr = lane >> 2, qc = lane & 3;
    const size_t rowG0 = (size_t)blockIdx.x * 256 + wid * 32 + qr;
    const uint32_t aHi = smem_base + M3_AHI, aLo = smem_base + M3_ALO;
    const uint32_t whi = smem_base + M3_WHI;

#pragma unroll 1
    for (int t = 0; t < T_; t++) {
        // phase 1: enc for own row (= tid)
        const size_t r = (size_t)blockIdx.x * 256 + tid;
        float a[32];
        const float4* hp = (const float4*)(g_h2 + ((size_t)t * B_ + r) * H_);
#pragma unroll
        for (int i = 0; i < 8; i++) {
            float4 v = hp[i];
            float2 s0 = g_bn2[t * 32 + i * 4 + 0]; a[i*4+0] = fmaxf(0.f, fmaf(v.x, s0.x, s0.y));
            float2 s1 = g_bn2[t * 32 + i * 4 + 1]; a[i*4+1] = fmaxf(0.f, fmaf(v.y, s1.x, s1.y));
            float2 s2 = g_bn2[t * 32 + i * 4 + 2]; a[i*4+2] = fmaxf(0.f, fmaf(v.z, s2.x, s2.y));
            float2 s3 = g_bn2[t * 32 + i * 4 + 3]; a[i*4+3] = fmaxf(0.f, fmaf(v.w, s3.x, s3.y));
        }
        float e[64];
#pragma unroll
        for (int j = 0; j < 64; j++) e[j] = __ldg(&b3[j]);
#pragma unroll
        for (int k = 0; k < 32; k++) {
            float ak = a[k];
#pragma unroll
            for (int q = 0; q < 16; q++) {
                float4 w = *(const float4*)&sW3[k * 64 + q * 4];
                e[q*4+0] = fmaf(w.x, ak, e[q*4+0]);
                e[q*4+1] = fmaf(w.y, ak, e[q*4+1]);
                e[q*4+2] = fmaf(w.z, ak, e[q*4+2]);
                e[q*4+3] = fmaf(w.w, ak, e[q*4+3]);
            }
        }
        {
            const uint32_t rb = (uint32_t)tid * 128u;
            const uint32_t rx = (uint32_t)(tid & 7) * 16u;
#pragma unroll
            for (int q = 0; q < 8; q++) {
                uint32_t off = rb + (((uint32_t)q * 16u) ^ rx);
                uint32_t ph[4], pl[4];
#pragma unroll
                for (int j = 0; j < 4; j++) {
                    float e0 = e[q*8 + 2*j], e1 = e[q*8 + 2*j + 1];
                    uint32_t p = pack_bf16(e0, e1);
                    ph[j] = p;
                    pl[j] = pack_bf16(e0 - __uint_as_float(p << 16),
                                      e1 - __uint_as_float(p & 0xffff0000u));
                }
                *(uint4*)(sm3 + M3_AHI + off) = make_uint4(ph[0], ph[1], ph[2], ph[3]);
                *(uint4*)(sm3 + M3_ALO + off) = make_uint4(pl[0], pl[1], pl[2], pl[3]);
            }
        }
        __syncwarp();

        // phase 2: xg = enc @ Wih^T + bsum via HMMA (warp-private rows)
        unsigned long long* xgt = g_xg + (size_t)t * 128 * B_;
#pragma unroll
        for (int cd = 0; cd < 4; cd++) {
            float acc[2][4][2][4];
#pragma unroll
            for (int mt = 0; mt < 2; mt++)
#pragma unroll
                for (int g = 0; g < 4; g++)
#pragma unroll
                    for (int ds = 0; ds < 2; ds++)
#pragma unroll
                        for (int z = 0; z < 4; z++) acc[mt][g][ds][z] = 0.f;
            const uint32_t brow_cd = (uint32_t)(cd * 16) * 128u + brow_l;
#pragma unroll
            for (int kt = 0; kt < 4; kt++) {
                const uint32_t acol = ((uint32_t)(kt * 32) + aoff16) ^ lxor;
                const uint32_t bcol = ((uint32_t)(kt * 32) + boff16) ^ lxor;
                uint32_t ah[2][4], al[2][4];
                ldsm4(ah[0], aHi + arow0 + acol);
                ldsm4(ah[1], aHi + arow0 + 2048u + acol);
                ldsm4(al[0], aLo + arow0 + acol);
                ldsm4(al[1], aLo + arow0 + 2048u + acol);
                uint32_t bh[4][4], bl[4][4];
#pragma unroll
                for (int g = 0; g < 4; g++) {
                    ldsm4(bh[g], whi + (uint32_t)g * 8192u + brow_cd + bcol);
                    ldsm4(bl[g], whi + 32768u + (uint32_t)g * 8192u + brow_cd + bcol);
                }
#pragma unroll
                for (int mt = 0; mt < 2; mt++)
#pragma unroll
                    for (int g = 0; g < 4; g++)
#pragma unroll
                        for (int ds = 0; ds < 2; ds++) {
                            mma_bf16(acc[mt][g][ds], ah[mt], bh[g][ds*2], bh[g][ds*2+1]);
                            mma_bf16(acc[mt][g][ds], al[mt], bh[g][ds*2], bh[g][ds*2+1]);
                            mma_bf16(acc[mt][g][ds], ah[mt], bl[g][ds*2], bl[g][ds*2+1]);
                        }
            }
#pragma unroll
            for (int g = 0; g < 4; g++)
#pragma unroll
                for (int ds = 0; ds < 2; ds++) {
                    const int pi = cd * 8 + ds * 4 + qc;
                    float2 bs = *(const float2*)&sb[g * 64 + 2 * pi];
#pragma unroll
                    for (int mt = 0; mt < 2; mt++)
#pragma unroll
                        for (int rr = 0; rr < 2; rr++) {
                            float v0 = acc[mt][g][ds][rr*2]     + bs.x;
                            float v1 = acc[mt][g][ds][rr*2 + 1] + bs.y;
                            unsigned long long pk;
                            PK64(v0, v1, pk);
                            xgt[(size_t)(g * 32 + pi) * B_ + rowG0 + mt * 16 + rr * 8] = pk;
                        }
                }
        }
        __syncwarp();
    }
}

// ---------------- stage 4: HMMA 28-step LSTM, grid 148 x 448 thr ----------------
// 14 warps/CTA, each warp owns 16-row group G = blockIdx.x + 148*wid (G < 2048)
#define LA_BUF   57344u
#define LA_LO    28672u
#define LW_OFF   114688u
#define LBIAS    180224u
#define LSTM_SMEM 181248

__global__ void __launch_bounds__(448, 1) k_lstm_mm(const float* __restrict__ bih,
                                                    const float* __restrict__ bhh,
                                                    float* __restrict__ out) {
    extern __shared__ __align__(16) uint8_t sm[];
    uint32_t smem_base;
    asm("{ .reg .u64 t; cvta.to.shared.u64 t, %1; cvt.u32.u64 %0, t; }"
        : "=r"(smem_base) : "l"(sm));
    float* sbsum = (float*)(sm + LBIAS);
    const int tid = threadIdx.x, wid = tid >> 5, lane = tid & 31;

    {   // Whh hi/lo tiles + biases
        const uint4* src = (const uint4*)g_wt;
        uint4* dst = (uint4*)(sm + LW_OFF);
        for (int i = tid; i < 65536 / 16; i += 448) dst[i] = src[i];
        if (tid < 256) sbsum[tid] = bih[tid] + bhh[tid];
    }
    __syncthreads();

    const int G = blockIdx.x + 148 * wid;          // 16-row group id
    const bool act = (G < 2048);
    const int l7 = lane & 7;
    const uint32_t lxor = (uint32_t)l7 * 16u;
    const uint32_t aoff16 = (uint32_t)((lane >> 4) & 1) * 16u;
    const uint32_t boff16 = (uint32_t)((lane >> 3) & 1) * 16u;
    const uint32_t arow0 = (uint32_t)(wid * 16 + l7 + ((lane >> 3) & 1) * 8) * 128u;
    const uint32_t brow_l = (uint32_t)(((lane >> 4) & 1) * 8 + l7) * 128u;
    const int qr = lane >> 2, qc = lane & 3;
    const int rowL0 = wid * 16 + qr;               // local A-tile row
    const size_t rowG0 = (size_t)G * 16 + qr;      // global row

    float c[32];
#pragma unroll
    for (int i = 0; i < 32; i++) c[i] = 0.f;

#pragma unroll 1
    for (int s = 0; s < 28; s++) {
        if (s == 4) {  // swap weights: Whh -> Wih+Whh
            __syncthreads();
            const uint4* src = (const uint4*)(g_wt + 65536);
            uint4* dst = (uint4*)(sm + LW_OFF);
            for (int i = tid; i < 65536 / 16; i += 448) dst[i] = src[i];
            __syncthreads();
        }
        const uint32_t aRd = smem_base + (uint32_t)((s + 1) & 1) * LA_BUF;
        uint8_t* aWr = sm + (uint32_t)(s & 1) * LA_BUF;
        const uint32_t whi = smem_base + LW_OFF;
        const int tsel = (s < 3) ? s : 2;
        const unsigned long long* xbase = g_xg + (size_t)tsel * 128 * B_;

#pragma unroll
        for (int cd = 0; cd < 4; cd++) {
            float acc[4][2][4];
#pragma unroll
            for (int g = 0; g < 4; g++)
#pragma unroll
                for (int ds = 0; ds < 2; ds++)
#pragma unroll
                    for (int z = 0; z < 4; z++) acc[g][ds][z] = 0.f;

            if (s >= 1) {
                const uint32_t brow_cd = (uint32_t)(cd * 16) * 128u + brow_l;
#pragma unroll
                for (int kt = 0; kt < 4; kt++) {
                    const uint32_t acol = ((uint32_t)(kt * 32) + aoff16) ^ lxor;
                    const uint32_t bcol = ((uint32_t)(kt * 32) + boff16) ^ lxor;
                    uint32_t ah[4], al[4];
                    ldsm4(ah, aRd + arow0 + acol);
                    ldsm4(al, aRd + LA_LO + arow0 + acol);
                    uint32_t bh[4][4], bl[4][4];
#pragma unroll
                    for (int g = 0; g < 4; g++) {
                        ldsm4(bh[g], whi + (uint32_t)g * 8192u + brow_cd + bcol);
                        ldsm4(bl[g], whi + 32768u + (uint32_t)g * 8192u + brow_cd + bcol);
                    }
#pragma unroll
                    for (int g = 0; g < 4; g++)
#pragma unroll
                        for (int ds = 0; ds < 2; ds++) {
                            mma_bf16(acc[g][ds], ah, bh[g][ds*2], bh[g][ds*2+1]);
                            mma_bf16(acc[g][ds], al, bh[g][ds*2], bh[g][ds*2+1]);
                            mma_bf16(acc[g][ds], ah, bl[g][ds*2], bl[g][ds*2+1]);
                        }
                }
            }

            // epilogue for this 16-d chunk
            const int pbase = cd * 8 + qc;
#pragma unroll
            for (int ds = 0; ds < 2; ds++) {
                const int dbase = cd * 16 + ds * 8 + 2 * qc;
                float2 bi, bf, bg, bo;
                if (s >= 4) {
                    bi = *(const float2*)&sbsum[0 * 64 + dbase];
                    bf = *(const float2*)&sbsum[1 * 64 + dbase];
                    bg = *(const float2*)&sbsum[2 * 64 + dbase];
                    bo = *(const float2*)&sbsum[3 * 64 + dbase];
                }
#pragma unroll
                for (int rr = 0; rr < 2; rr++) {
                    const int rowL = rowL0 + rr * 8;
                    float gi0 = acc[0][ds][rr*2], gi1 = acc[0][ds][rr*2+1];
                    float gf0 = acc[1][ds][rr*2], gf1 = acc[1][ds][rr*2+1];
                    float gg0 = acc[2][ds][rr*2], gg1 = acc[2][ds][rr*2+1];
                    float go0 = acc[3][ds][rr*2], go1 = acc[3][ds][rr*2+1];
                    if (s < 4) {
                        const int pi = pbase + ds * 4;
                        float lo, hi;
                        unsigned long long v;
                        if (act) {
                            const unsigned long long* xp = xbase + (rowG0 + rr * 8);
                            v = xp[(size_t)(0 * 32 + pi) * B_]; UNPK(v, lo, hi); gi0 += lo; gi1 += hi;
                            v = xp[(size_t)(1 * 32 + pi) * B_]; UNPK(v, lo, hi); gf0 += lo; gf1 += hi;
                            v = xp[(size_t)(2 * 32 + pi) * B_]; UNPK(v, lo, hi); gg0 += lo; gg1 += hi;
                            v = xp[(size_t)(3 * 32 + pi) * B_]; UNPK(v, lo, hi); go0 += lo; go1 += hi;
                        }
                    } else {
                        gi0 += bi.x; gi1 += bi.y;
                        gf0 += bf.x; gf1 += bf.y;
                        gg0 += bg.x; gg1 += bg.y;
                        go0 += bo.x; go1 += bo.y;
                    }
                    const int ci = ((cd * 2 + ds) * 2 + rr) * 2;
                    float h0, h1;
                    lstm_cell2(gi0, gf0, gg0, go0, gi1, gf1, gg1, go1,
                               c[ci], c[ci + 1], h0, h1);
                    // split h into bf16 hi/lo and store to next-step A tile
                    uint32_t ph = pack_bf16(h0, h1);
                    float e0 = h0 - __uint_as_float(ph << 16);
                    float e1 = h1 - __uint_as_float(ph & 0xffff0000u);
                    uint32_t pl = pack_bf16(e0, e1);
                    uint32_t soff = (uint32_t)rowL * 128u +
                                    (((uint32_t)(cd * 32 + ds * 16 + qc * 4)) ^ ((uint32_t)qr * 16u));
                    *(uint32_t*)(aWr + soff) = ph;
                    *(uint32_t*)(aWr + LA_LO + soff) = pl;
                    if (s >= 3 && act) {
                        float2 o2 = make_float2(h0, h1);
                        *(float2*)(out + ((rowG0 + rr * 8) * 25 + (s - 3)) * 64 + dbase) = o2;
                    }
                }
            }
        }
        __syncwarp();
    }
}

// ---------------- host ----------------
extern "C" void kernel_launch(void* const* d_in, const int* in_sizes, int n_in,
                              void* d_out, int out_size) {
    const float* x   = (const float*)d_in[0];
    const float* W1  = (const float*)d_in[1];
    const float* b1  = (const float*)d_in[2];
    const float* g1  = (const float*)d_in[3];
    const float* be1 = (const float*)d_in[4];
    const float* W2  = (const float*)d_in[5];
    const float* b2  = (const float*)d_in[6];
    const float* g2  = (const float*)d_in[7];
    const float* be2 = (const float*)d_in[8];
    const float* W3  = (const float*)d_in[9];
    const float* b3  = (const float*)d_in[10];
    const float* Wih = (const float*)d_in[11];
    const float* Whh = (const float*)d_in[12];
    const float* bih = (const float*)d_in[13];
    const float* bhh = (const float*)d_in[14];
    float* out = (float*)d_out;

    static bool attr_done = false;
    if (!attr_done) {
        cudaFuncSetAttribute(k_mlp3, cudaFuncAttributeMaxDynamicSharedMemorySize, M3_SMEM);
        cudaFuncSetAttribute(k_lstm_mm, cudaFuncAttributeMaxDynamicSharedMemorySize, LSTM_SMEM);
        attr_done = true;
    }

    dim3 gmlp(NBLK, T_);
    k_mlp1<<<gmlp, 256>>>(x, W1, b1, g1, be1, Wih, Whh);
    k_mlp2<<<gmlp, 256>>>(W2, b2, g2, be2);
    k_mlp3<<<NBLK, 256, M3_SMEM>>>(W3, b3, bih, bhh);
    k_lstm_mm<<<148, 448, LSTM_SMEM>>>(bih, bhh, out);
}